// round 1
// baseline (speedup 1.0000x reference)
#include <cuda_runtime.h>
#include <cuda_bf16.h>
#include <math.h>

// ---------------- problem constants ----------------
#define BS   8
#define SEQ  1024
#define DM   768
#define NH   4
#define DH   192
#define ROWS (BS*SEQ)          // 8192
#define D3   (3*DM)            // 2304
#define D4   (4*DM)            // 3072

#define XOUT_ELEMS   ((size_t)ROWS*DM)                    // 6,291,456
#define PRES_ELEMS   ((size_t)BS*2*NH*SEQ*DH)             // 12,582,912

// ---------------- scratch (device globals: no allocation allowed) ---------
__device__ float g_xn [ROWS*DM];
__device__ float g_qkv[(size_t)ROWS*D3];
__device__ float g_att[ROWS*DM];
__device__ float g_x1 [ROWS*DM];
__device__ float g_xn2[ROWS*DM];
__device__ float g_h  [(size_t)ROWS*D4];

// ---------------- LayerNorm: one block per row (768 cols) -----------------
__global__ __launch_bounds__(256) void ln_kernel(
    const float* __restrict__ x, const float* __restrict__ gamma,
    const float* __restrict__ beta, float* __restrict__ out)
{
    int row = blockIdx.x;
    int tid = threadIdx.x;
    const float* xr = x + (size_t)row * DM;
    float v0 = xr[tid], v1 = xr[tid + 256], v2 = xr[tid + 512];
    float s  = v0 + v1 + v2;
    float sq = v0*v0 + v1*v1 + v2*v2;
    #pragma unroll
    for (int o = 16; o > 0; o >>= 1) {
        s  += __shfl_xor_sync(0xffffffffu, s,  o);
        sq += __shfl_xor_sync(0xffffffffu, sq, o);
    }
    __shared__ float ss[8], ssq[8];
    __shared__ float mu_s, rs_s;
    int w = tid >> 5, l = tid & 31;
    if (l == 0) { ss[w] = s; ssq[w] = sq; }
    __syncthreads();
    if (tid == 0) {
        float S = 0.f, SQ = 0.f;
        #pragma unroll
        for (int i = 0; i < 8; i++) { S += ss[i]; SQ += ssq[i]; }
        float mu = S * (1.0f / DM);
        float var = SQ * (1.0f / DM) - mu * mu;
        mu_s = mu;
        rs_s = rsqrtf(var + 1e-3f);
    }
    __syncthreads();
    float mu = mu_s, rs = rs_s;
    float* orow = out + (size_t)row * DM;
    orow[tid      ] = (v0 - mu) * rs * gamma[tid      ] + beta[tid      ];
    orow[tid + 256] = (v1 - mu) * rs * gamma[tid + 256] + beta[tid + 256];
    orow[tid + 512] = (v2 - mu) * rs * gamma[tid + 512] + beta[tid + 512];
}

// ---------------- GELU (tanh approximation, matches reference) ------------
__device__ __forceinline__ float gelu_tanh_f(float x) {
    float x3 = x * x * x;
    float t  = tanhf(0.7978845608028654f * (x + 0.044715f * x3));
    return 0.5f * x * (1.0f + t);
}

// ---------------- SGEMM: C = A@B + bias (+res) (gelu?) --------------------
// A[M,K] row-major, B[K,N] row-major. Tiles 128x128x8, 256 threads, 8x8/thr.
template <bool GELU>
__global__ __launch_bounds__(256) void sgemm_kernel(
    const float* __restrict__ A, const float* __restrict__ B,
    const float* __restrict__ bias, const float* __restrict__ res,
    float* __restrict__ C, int M, int N, int K)
{
    __shared__ float As[8][128];
    __shared__ float Bs[8][128];

    int bx = blockIdx.x;      // N tile
    int by = blockIdx.y;      // M tile
    int tid = threadIdx.x;
    int tx = tid & 15, ty = tid >> 4;

    const float* Ab = A + (size_t)(by * 128) * K;
    const float* Bb = B + (size_t)bx * 128;

    int a_row = tid >> 1, a_col = (tid & 1) * 4;
    int b_row = tid >> 5, b_col = (tid & 31) * 4;

    float acc[8][8];
    #pragma unroll
    for (int i = 0; i < 8; i++)
        #pragma unroll
        for (int j = 0; j < 8; j++) acc[i][j] = 0.f;

    for (int k0 = 0; k0 < K; k0 += 8) {
        float4 av = *reinterpret_cast<const float4*>(Ab + (size_t)a_row * K + k0 + a_col);
        As[a_col + 0][a_row] = av.x;
        As[a_col + 1][a_row] = av.y;
        As[a_col + 2][a_row] = av.z;
        As[a_col + 3][a_row] = av.w;
        float4 bv = *reinterpret_cast<const float4*>(Bb + (size_t)(k0 + b_row) * N + b_col);
        *reinterpret_cast<float4*>(&Bs[b_row][b_col]) = bv;
        __syncthreads();
        #pragma unroll
        for (int kk = 0; kk < 8; kk++) {
            float a_frag[8], b_frag[8];
            *(float4*)&a_frag[0] = *(float4*)&As[kk][ty * 8];
            *(float4*)&a_frag[4] = *(float4*)&As[kk][ty * 8 + 4];
            *(float4*)&b_frag[0] = *(float4*)&Bs[kk][tx * 8];
            *(float4*)&b_frag[4] = *(float4*)&Bs[kk][tx * 8 + 4];
            #pragma unroll
            for (int i = 0; i < 8; i++)
                #pragma unroll
                for (int j = 0; j < 8; j++)
                    acc[i][j] = fmaf(a_frag[i], b_frag[j], acc[i][j]);
        }
        __syncthreads();
    }

    int row0 = by * 128 + ty * 8;
    int col0 = bx * 128 + tx * 8;
    float bv[8];
    #pragma unroll
    for (int j = 0; j < 8; j++) bv[j] = bias[col0 + j];
    #pragma unroll
    for (int i = 0; i < 8; i++) {
        size_t roff = (size_t)(row0 + i) * N + col0;
        #pragma unroll
        for (int j = 0; j < 8; j++) {
            float v = acc[i][j] + bv[j];
            if (res) v += res[roff + j];
            if (GELU) v = gelu_tanh_f(v);
            C[roff + j] = v;
        }
    }
}

// ---------------- present copy: qkv -> out[B,2,H,S,dh] ---------------------
__global__ __launch_bounds__(256) void present_kernel(
    const float* __restrict__ qkv, float* __restrict__ out)
{
    size_t idx = (size_t)blockIdx.x * blockDim.x + threadIdx.x;
    if (idx >= PRES_ELEMS) return;
    int d = (int)(idx % DH); size_t t = idx / DH;
    int s = (int)(t % SEQ);  t /= SEQ;
    int h = (int)(t % NH);   t /= NH;
    int kv = (int)(t % 2);
    int b  = (int)(t / 2);
    out[idx] = qkv[((size_t)(b * SEQ + s)) * D3 + (size_t)(kv + 1) * DM + h * DH + d];
}

// ---------------- flash attention (fp32, causal, score *= sqrt(dh)) --------
// one block per (q-tile of 64, head, batch); 256 threads (16x16)
#define QS_STRIDE 65
#define PS_STRIDE 66
#define ATT_SMEM_FLOATS (192*QS_STRIDE*2 + 64*192 + 64*PS_STRIDE + 64*3)
#define ATT_SMEM_BYTES  (ATT_SMEM_FLOATS*4)

__global__ __launch_bounds__(256) void attention_kernel(
    const float* __restrict__ qkv, float* __restrict__ attn)
{
    extern __shared__ float sm[];
    float* Qs   = sm;                          // [192][65]  transposed Q
    float* Ks   = Qs + 192 * QS_STRIDE;        // [192][65]  transposed K
    float* Vs   = Ks + 192 * QS_STRIDE;        // [64][192]
    float* Ps   = Vs + 64 * 192;               // [64][66]
    float* mrow = Ps + 64 * PS_STRIDE;         // [64]
    float* lrow = mrow + 64;
    float* crow = lrow + 64;

    int bi = blockIdx.x;   // q tile (0..15)
    int h  = blockIdx.y;
    int b  = blockIdx.z;
    int tid = threadIdx.x;
    int tx = tid & 15, ty = tid >> 4;

    const float* qbase = qkv + ((size_t)(b * SEQ + bi * 64)) * D3 + h * DH;

    for (int idx = tid; idx < 64 * DH; idx += 256) {
        int q = idx / DH, d = idx % DH;
        Qs[d * QS_STRIDE + q] = qbase[(size_t)q * D3 + d];
    }
    if (tid < 64) { mrow[tid] = -1e30f; lrow[tid] = 0.f; }

    float O[4][12];
    #pragma unroll
    for (int r = 0; r < 4; r++)
        #pragma unroll
        for (int d = 0; d < 12; d++) O[r][d] = 0.f;

    const float scale = 13.856406460551018f;   // sqrt(192)  (faithful bug)

    for (int j = 0; j <= bi; j++) {
        __syncthreads();   // protect Ks/Vs/Ps from previous iteration + Q load
        const float* kbase = qkv + ((size_t)(b * SEQ + j * 64)) * D3 + DM + h * DH;
        const float* vbase = kbase + DM;
        for (int idx = tid; idx < 64 * DH; idx += 256) {
            int k = idx / DH, d = idx % DH;
            Ks[d * QS_STRIDE + k] = kbase[(size_t)k * D3 + d];
            Vs[k * DH + d]        = vbase[(size_t)k * D3 + d];
        }
        __syncthreads();

        // scores: 64x64, each thread 4x4
        float sacc[4][4];
        #pragma unroll
        for (int r = 0; r < 4; r++)
            #pragma unroll
            for (int c = 0; c < 4; c++) sacc[r][c] = 0.f;
        #pragma unroll 4
        for (int kk = 0; kk < DH; kk++) {
            float a0 = Qs[kk * QS_STRIDE + ty * 4 + 0];
            float a1 = Qs[kk * QS_STRIDE + ty * 4 + 1];
            float a2 = Qs[kk * QS_STRIDE + ty * 4 + 2];
            float a3 = Qs[kk * QS_STRIDE + ty * 4 + 3];
            float b0 = Ks[kk * QS_STRIDE + tx * 4 + 0];
            float b1 = Ks[kk * QS_STRIDE + tx * 4 + 1];
            float b2 = Ks[kk * QS_STRIDE + tx * 4 + 2];
            float b3 = Ks[kk * QS_STRIDE + tx * 4 + 3];
            sacc[0][0] = fmaf(a0,b0,sacc[0][0]); sacc[0][1] = fmaf(a0,b1,sacc[0][1]);
            sacc[0][2] = fmaf(a0,b2,sacc[0][2]); sacc[0][3] = fmaf(a0,b3,sacc[0][3]);
            sacc[1][0] = fmaf(a1,b0,sacc[1][0]); sacc[1][1] = fmaf(a1,b1,sacc[1][1]);
            sacc[1][2] = fmaf(a1,b2,sacc[1][2]); sacc[1][3] = fmaf(a1,b3,sacc[1][3]);
            sacc[2][0] = fmaf(a2,b0,sacc[2][0]); sacc[2][1] = fmaf(a2,b1,sacc[2][1]);
            sacc[2][2] = fmaf(a2,b2,sacc[2][2]); sacc[2][3] = fmaf(a2,b3,sacc[2][3]);
            sacc[3][0] = fmaf(a3,b0,sacc[3][0]); sacc[3][1] = fmaf(a3,b1,sacc[3][1]);
            sacc[3][2] = fmaf(a3,b2,sacc[3][2]); sacc[3][3] = fmaf(a3,b3,sacc[3][3]);
        }
        int qg0 = bi * 64 + ty * 4;
        int kg0 = j  * 64 + tx * 4;
        #pragma unroll
        for (int r = 0; r < 4; r++)
            #pragma unroll
            for (int c = 0; c < 4; c++) {
                float v = sacc[r][c] * scale;
                if (j == bi && (kg0 + c) > (qg0 + r)) v = -1e30f;
                Ps[(ty * 4 + r) * PS_STRIDE + tx * 4 + c] = v;
            }
        __syncthreads();

        // online softmax row pass (64 threads, one per row)
        if (tid < 64) {
            float m_old = mrow[tid];
            float mx = m_old;
            float* pr = &Ps[tid * PS_STRIDE];
            #pragma unroll 8
            for (int c = 0; c < 64; c++) mx = fmaxf(mx, pr[c]);
            float corr = __expf(m_old - mx);
            float sum = 0.f;
            #pragma unroll 8
            for (int c = 0; c < 64; c++) {
                float p = __expf(pr[c] - mx);
                pr[c] = p;
                sum += p;
            }
            lrow[tid] = lrow[tid] * corr + sum;
            mrow[tid] = mx;
            crow[tid] = corr;
        }
        __syncthreads();

        // O = O*corr + P @ V
        float cr[4];
        #pragma unroll
        for (int r = 0; r < 4; r++) cr[r] = crow[ty * 4 + r];
        #pragma unroll
        for (int r = 0; r < 4; r++)
            #pragma unroll
            for (int d = 0; d < 12; d++) O[r][d] *= cr[r];
        #pragma unroll 2
        for (int kk = 0; kk < 64; kk++) {
            float p0 = Ps[(ty * 4 + 0) * PS_STRIDE + kk];
            float p1 = Ps[(ty * 4 + 1) * PS_STRIDE + kk];
            float p2 = Ps[(ty * 4 + 2) * PS_STRIDE + kk];
            float p3 = Ps[(ty * 4 + 3) * PS_STRIDE + kk];
            float vv[12];
            *(float4*)&vv[0] = *(float4*)&Vs[kk * DH + tx * 12 + 0];
            *(float4*)&vv[4] = *(float4*)&Vs[kk * DH + tx * 12 + 4];
            *(float4*)&vv[8] = *(float4*)&Vs[kk * DH + tx * 12 + 8];
            #pragma unroll
            for (int d = 0; d < 12; d++) {
                O[0][d] = fmaf(p0, vv[d], O[0][d]);
                O[1][d] = fmaf(p1, vv[d], O[1][d]);
                O[2][d] = fmaf(p2, vv[d], O[2][d]);
                O[3][d] = fmaf(p3, vv[d], O[3][d]);
            }
        }
    }

    // final normalize + write [row][h*DH + d]
    float* ob = attn + ((size_t)(b * SEQ + bi * 64)) * DM + h * DH;
    #pragma unroll
    for (int r = 0; r < 4; r++) {
        float linv = 1.0f / lrow[ty * 4 + r];
        #pragma unroll
        for (int d = 0; d < 12; d++)
            ob[(size_t)(ty * 4 + r) * DM + tx * 12 + d] = O[r][d] * linv;
    }
}

// ---------------- launch -----------------------------------------------
extern "C" void kernel_launch(void* const* d_in, const int* in_sizes, int n_in,
                              void* d_out, int out_size)
{
    const float* x   = (const float*)d_in[0];
    // d_in[1] = mask (causal, handled analytically)
    const float* W1  = (const float*)d_in[2];
    const float* b1  = (const float*)d_in[3];
    const float* W3  = (const float*)d_in[4];
    const float* b3  = (const float*)d_in[5];
    const float* W2  = (const float*)d_in[6];
    const float* b2  = (const float*)d_in[7];
    const float* W4  = (const float*)d_in[8];
    const float* b4  = (const float*)d_in[9];
    const float* g1  = (const float*)d_in[10];
    const float* be1 = (const float*)d_in[11];
    const float* g2  = (const float*)d_in[12];
    const float* be2 = (const float*)d_in[13];
    float* out = (float*)d_out;

    float *xn, *qkv, *att, *x1, *xn2, *hbuf;
    cudaGetSymbolAddress((void**)&xn,   g_xn);
    cudaGetSymbolAddress((void**)&qkv,  g_qkv);
    cudaGetSymbolAddress((void**)&att,  g_att);
    cudaGetSymbolAddress((void**)&x1,   g_x1);
    cudaGetSymbolAddress((void**)&xn2,  g_xn2);
    cudaGetSymbolAddress((void**)&hbuf, g_h);

    cudaFuncSetAttribute(attention_kernel,
                         cudaFuncAttributeMaxDynamicSharedMemorySize, ATT_SMEM_BYTES);

    // 1) LN1
    ln_kernel<<<ROWS, 256>>>(x, g1, be1, xn);

    // 2) qkv = xn @ W1 + b1
    sgemm_kernel<false><<<dim3(D3/128, ROWS/128), 256>>>(xn, W1, b1, nullptr, qkv, ROWS, D3, DM);

    // 3) present output (if present region exists)
    if ((size_t)out_size >= XOUT_ELEMS + PRES_ELEMS) {
        present_kernel<<<(int)((PRES_ELEMS + 255) / 256), 256>>>(qkv, out + XOUT_ELEMS);
    }

    // 4) attention
    attention_kernel<<<dim3(SEQ/64, NH, BS), 256, ATT_SMEM_BYTES>>>(qkv, att);

    // 5) x1 = att @ W3 + b3 + x
    sgemm_kernel<false><<<dim3(DM/128, ROWS/128), 256>>>(att, W3, b3, x, x1, ROWS, DM, DM);

    // 6) LN2
    ln_kernel<<<ROWS, 256>>>(x1, g2, be2, xn2);

    // 7) h = gelu(xn2 @ W2 + b2)
    sgemm_kernel<true><<<dim3(D4/128, ROWS/128), 256>>>(xn2, W2, b2, nullptr, hbuf, ROWS, D4, DM);

    // 8) out = h @ W4 + b4 + x1
    sgemm_kernel<false><<<dim3(DM/128, ROWS/128), 256>>>(hbuf, W4, b4, x1, out, ROWS, DM, D4);
}

// round 2
// speedup vs baseline: 1.5619x; 1.5619x over previous
#include <cuda_runtime.h>
#include <cuda_bf16.h>
#include <math.h>

// ---------------- problem constants ----------------
#define BS   8
#define SEQ  1024
#define DM   768
#define NH   4
#define DH   192
#define ROWS (BS*SEQ)          // 8192
#define D3   (3*DM)            // 2304
#define D4   (4*DM)            // 3072

#define XOUT_ELEMS   ((size_t)ROWS*DM)
#define PRES_ELEMS   ((size_t)BS*2*NH*SEQ*DH)

// ---------------- scratch (device globals) ---------------------------------
__device__ float g_xn [ROWS*DM];
__device__ float g_qkv[(size_t)ROWS*D3];
__device__ float g_att[ROWS*DM];
__device__ float g_x1 [ROWS*DM];
__device__ float g_xn2[ROWS*DM];
__device__ float g_h  [(size_t)ROWS*D4];

// ---------------- LayerNorm -------------------------------------------------
__global__ __launch_bounds__(256) void ln_kernel(
    const float* __restrict__ x, const float* __restrict__ gamma,
    const float* __restrict__ beta, float* __restrict__ out)
{
    int row = blockIdx.x;
    int tid = threadIdx.x;
    const float* xr = x + (size_t)row * DM;
    float v0 = xr[tid], v1 = xr[tid + 256], v2 = xr[tid + 512];
    float s  = v0 + v1 + v2;
    float sq = v0*v0 + v1*v1 + v2*v2;
    #pragma unroll
    for (int o = 16; o > 0; o >>= 1) {
        s  += __shfl_xor_sync(0xffffffffu, s,  o);
        sq += __shfl_xor_sync(0xffffffffu, sq, o);
    }
    __shared__ float ss[8], ssq[8];
    __shared__ float mu_s, rs_s;
    int w = tid >> 5, l = tid & 31;
    if (l == 0) { ss[w] = s; ssq[w] = sq; }
    __syncthreads();
    if (tid == 0) {
        float S = 0.f, SQ = 0.f;
        #pragma unroll
        for (int i = 0; i < 8; i++) { S += ss[i]; SQ += ssq[i]; }
        float mu = S * (1.0f / DM);
        float var = SQ * (1.0f / DM) - mu * mu;
        mu_s = mu;
        rs_s = rsqrtf(var + 1e-3f);
    }
    __syncthreads();
    float mu = mu_s, rs = rs_s;
    float* orow = out + (size_t)row * DM;
    orow[tid      ] = (v0 - mu) * rs * gamma[tid      ] + beta[tid      ];
    orow[tid + 256] = (v1 - mu) * rs * gamma[tid + 256] + beta[tid + 256];
    orow[tid + 512] = (v2 - mu) * rs * gamma[tid + 512] + beta[tid + 512];
}

// ---------------- GELU ------------------------------------------------------
__device__ __forceinline__ float gelu_tanh_f(float x) {
    float x3 = x * x * x;
    float t  = tanhf(0.7978845608028654f * (x + 0.044715f * x3));
    return 0.5f * x * (1.0f + t);
}

// ---------------- bf16 split + mma helpers ---------------------------------
__device__ __forceinline__ void split2(float x0, float x1, unsigned &hi, unsigned &lo) {
    __nv_bfloat16 h0 = __float2bfloat16_rn(x0);
    __nv_bfloat16 h1 = __float2bfloat16_rn(x1);
    __nv_bfloat16 l0 = __float2bfloat16_rn(x0 - __bfloat162float(h0));
    __nv_bfloat16 l1 = __float2bfloat16_rn(x1 - __bfloat162float(h1));
    hi = ((unsigned)__bfloat16_as_ushort(h1) << 16) | (unsigned)__bfloat16_as_ushort(h0);
    lo = ((unsigned)__bfloat16_as_ushort(l1) << 16) | (unsigned)__bfloat16_as_ushort(l0);
}

__device__ __forceinline__ void mma_bf16(float c[4], const unsigned a[4], const unsigned b[2]) {
    asm volatile(
        "mma.sync.aligned.m16n8k16.row.col.f32.bf16.bf16.f32 "
        "{%0,%1,%2,%3}, {%4,%5,%6,%7}, {%8,%9}, {%0,%1,%2,%3};\n"
        : "+f"(c[0]), "+f"(c[1]), "+f"(c[2]), "+f"(c[3])
        : "r"(a[0]), "r"(a[1]), "r"(a[2]), "r"(a[3]), "r"(b[0]), "r"(b[1]));
}

// ---------------- split-bf16 tensor-core GEMM -------------------------------
// C[M,N] = A[M,K] @ B[K,N] + bias (+res) (gelu?)
// block tile 128x128x32, 256 threads = 8 warps (2 M x 4 N), warp tile 64x32.
// smem: u32 words over (row, k-pair), stride 20 (conflict-free frag loads).
#define SST 20

template<bool GELU>
__global__ __launch_bounds__(256) void bgemm_kernel(
    const float* __restrict__ A, const float* __restrict__ B,
    const float* __restrict__ bias, const float* __restrict__ res,
    float* __restrict__ C, int M, int N, int K)
{
    __shared__ unsigned As_hi[128*SST], As_lo[128*SST];
    __shared__ unsigned Bs_hi[128*SST], Bs_lo[128*SST];

    const int tid = threadIdx.x;
    const int w = tid >> 5, l = tid & 31;
    const int wm = w & 1, wn = w >> 1;
    const int gid = l >> 2, tig = l & 3;
    const int bx = blockIdx.x, by = blockIdx.y;

    const float* Ab = A + (size_t)(by * 128) * K;
    const float* Bb = B + bx * 128;

    float acc[4][4][4];
    #pragma unroll
    for (int i = 0; i < 4; i++)
        #pragma unroll
        for (int j = 0; j < 4; j++)
            #pragma unroll
            for (int c = 0; c < 4; c++) acc[i][j][c] = 0.f;

    // register staging for software pipeline
    float4 a_st[4];
    float  b_st[4][4];

    const int ntiles = K >> 5;

    // ---- load one 128x32 A tile + 32x128 B tile into registers ----
    auto load_tile = [&](int k0) {
        #pragma unroll
        for (int i = 0; i < 4; i++) {
            int s = tid + (i << 8);            // 1024 slots
            int m = s >> 3, kv = s & 7;        // lanes: same m per 8 lanes, coalesced 128B
            a_st[i] = *reinterpret_cast<const float4*>(Ab + (size_t)m * K + k0 + (kv << 2));
        }
        #pragma unroll
        for (int i = 0; i < 4; i++) {
            int s = tid + (i << 8);
            int n = s & 127, k4 = s >> 7;      // lanes: consecutive n -> coalesced
            int k = k0 + (k4 << 2);
            const float* bp = Bb + (size_t)k * N + n;
            #pragma unroll
            for (int j = 0; j < 4; j++) b_st[i][j] = bp[(size_t)j * N];
        }
    };

    auto store_tile = [&]() {
        #pragma unroll
        for (int i = 0; i < 4; i++) {
            int s = tid + (i << 8);
            int m = s >> 3, kv = s & 7;
            int kp = kv << 1;
            unsigned h0, l0, h1, l1;
            split2(a_st[i].x, a_st[i].y, h0, l0);
            split2(a_st[i].z, a_st[i].w, h1, l1);
            As_hi[m * SST + kp] = h0; As_hi[m * SST + kp + 1] = h1;
            As_lo[m * SST + kp] = l0; As_lo[m * SST + kp + 1] = l1;
        }
        #pragma unroll
        for (int i = 0; i < 4; i++) {
            int s = tid + (i << 8);
            int n = s & 127, k4 = s >> 7;
            int kp = k4 << 1;
            unsigned h0, l0, h1, l1;
            split2(b_st[i][0], b_st[i][1], h0, l0);
            split2(b_st[i][2], b_st[i][3], h1, l1);
            Bs_hi[n * SST + kp] = h0; Bs_hi[n * SST + kp + 1] = h1;
            Bs_lo[n * SST + kp] = l0; Bs_lo[n * SST + kp + 1] = l1;
        }
    };

    load_tile(0);
    store_tile();
    __syncthreads();

    for (int t = 0; t < ntiles; t++) {
        if (t + 1 < ntiles) load_tile((t + 1) << 5);   // prefetch next tile into regs

        #pragma unroll
        for (int ks = 0; ks < 2; ks++) {
            const int kp0 = ks << 3;
            unsigned ah[4][4], al[4][4], bh[4][2], bl[4][2];
            #pragma unroll
            for (int am = 0; am < 4; am++) {
                int mrow = wm * 64 + am * 16;
                int base0 = (mrow + gid) * SST + kp0 + tig;
                int base1 = (mrow + gid + 8) * SST + kp0 + tig;
                ah[am][0] = As_hi[base0];     ah[am][1] = As_hi[base1];
                ah[am][2] = As_hi[base0 + 4]; ah[am][3] = As_hi[base1 + 4];
                al[am][0] = As_lo[base0];     al[am][1] = As_lo[base1];
                al[am][2] = As_lo[base0 + 4]; al[am][3] = As_lo[base1 + 4];
            }
            #pragma unroll
            for (int an = 0; an < 4; an++) {
                int ncol = wn * 32 + an * 8;
                int base = (ncol + gid) * SST + kp0 + tig;
                bh[an][0] = Bs_hi[base]; bh[an][1] = Bs_hi[base + 4];
                bl[an][0] = Bs_lo[base]; bl[an][1] = Bs_lo[base + 4];
            }
            #pragma unroll
            for (int am = 0; am < 4; am++)
                #pragma unroll
                for (int an = 0; an < 4; an++) {
                    mma_bf16(acc[am][an], ah[am], bh[an]);
                    mma_bf16(acc[am][an], al[am], bh[an]);
                    mma_bf16(acc[am][an], ah[am], bl[an]);
                }
        }
        __syncthreads();
        if (t + 1 < ntiles) store_tile();
        __syncthreads();
    }

    // ---- epilogue ----
    #pragma unroll
    for (int am = 0; am < 4; am++) {
        int m0 = by * 128 + wm * 64 + am * 16;
        int r0 = m0 + gid, r1 = m0 + gid + 8;
        #pragma unroll
        for (int an = 0; an < 4; an++) {
            int n0 = bx * 128 + wn * 32 + an * 8 + 2 * tig;
            float bv0 = bias[n0], bv1 = bias[n0 + 1];
            size_t o0 = (size_t)r0 * N + n0;
            size_t o1 = (size_t)r1 * N + n0;
            float v0 = acc[am][an][0] + bv0;
            float v1 = acc[am][an][1] + bv1;
            float v2 = acc[am][an][2] + bv0;
            float v3 = acc[am][an][3] + bv1;
            if (res) {
                v0 += res[o0]; v1 += res[o0 + 1];
                v2 += res[o1]; v3 += res[o1 + 1];
            }
            if (GELU) {
                v0 = gelu_tanh_f(v0); v1 = gelu_tanh_f(v1);
                v2 = gelu_tanh_f(v2); v3 = gelu_tanh_f(v3);
            }
            *reinterpret_cast<float2*>(C + o0) = make_float2(v0, v1);
            *reinterpret_cast<float2*>(C + o1) = make_float2(v2, v3);
        }
    }
}

// ---------------- present copy: qkv -> out[B,2,H,S,dh] ----------------------
__global__ __launch_bounds__(256) void present_kernel(
    const float* __restrict__ qkv, float* __restrict__ out)
{
    size_t idx = (size_t)blockIdx.x * blockDim.x + threadIdx.x;
    if (idx >= PRES_ELEMS) return;
    int d = (int)(idx % DH); size_t t = idx / DH;
    int s = (int)(t % SEQ);  t /= SEQ;
    int h = (int)(t % NH);   t /= NH;
    int kv = (int)(t % 2);
    int b  = (int)(t / 2);
    out[idx] = qkv[((size_t)(b * SEQ + s)) * D3 + (size_t)(kv + 1) * DM + h * DH + d];
}

// ---------------- flash attention (fp32, causal, score *= sqrt(dh)) ---------
#define QS_STRIDE 65
#define PS_STRIDE 66
#define ATT_SMEM_FLOATS (192*QS_STRIDE*2 + 64*192 + 64*PS_STRIDE + 64*3)
#define ATT_SMEM_BYTES  (ATT_SMEM_FLOATS*4)

__global__ __launch_bounds__(256) void attention_kernel(
    const float* __restrict__ qkv, float* __restrict__ attn)
{
    extern __shared__ float sm[];
    float* Qs   = sm;
    float* Ks   = Qs + 192 * QS_STRIDE;
    float* Vs   = Ks + 192 * QS_STRIDE;
    float* Ps   = Vs + 64 * 192;
    float* mrow = Ps + 64 * PS_STRIDE;
    float* lrow = mrow + 64;
    float* crow = lrow + 64;

    int bi = blockIdx.x;
    int h  = blockIdx.y;
    int b  = blockIdx.z;
    int tid = threadIdx.x;
    int tx = tid & 15, ty = tid >> 4;

    const float* qbase = qkv + ((size_t)(b * SEQ + bi * 64)) * D3 + h * DH;

    for (int idx = tid; idx < 64 * DH; idx += 256) {
        int q = idx / DH, d = idx % DH;
        Qs[d * QS_STRIDE + q] = qbase[(size_t)q * D3 + d];
    }
    if (tid < 64) { mrow[tid] = -1e30f; lrow[tid] = 0.f; }

    float O[4][12];
    #pragma unroll
    for (int r = 0; r < 4; r++)
        #pragma unroll
        for (int d = 0; d < 12; d++) O[r][d] = 0.f;

    const float scale = 13.856406460551018f;   // sqrt(192) (faithful bug)

    for (int j = 0; j <= bi; j++) {
        __syncthreads();
        const float* kbase = qkv + ((size_t)(b * SEQ + j * 64)) * D3 + DM + h * DH;
        const float* vbase = kbase + DM;
        for (int idx = tid; idx < 64 * DH; idx += 256) {
            int k = idx / DH, d = idx % DH;
            Ks[d * QS_STRIDE + k] = kbase[(size_t)k * D3 + d];
            Vs[k * DH + d]        = vbase[(size_t)k * D3 + d];
        }
        __syncthreads();

        float sacc[4][4];
        #pragma unroll
        for (int r = 0; r < 4; r++)
            #pragma unroll
            for (int c = 0; c < 4; c++) sacc[r][c] = 0.f;
        #pragma unroll 4
        for (int kk = 0; kk < DH; kk++) {
            float a0 = Qs[kk * QS_STRIDE + ty * 4 + 0];
            float a1 = Qs[kk * QS_STRIDE + ty * 4 + 1];
            float a2 = Qs[kk * QS_STRIDE + ty * 4 + 2];
            float a3 = Qs[kk * QS_STRIDE + ty * 4 + 3];
            float b0 = Ks[kk * QS_STRIDE + tx * 4 + 0];
            float b1 = Ks[kk * QS_STRIDE + tx * 4 + 1];
            float b2 = Ks[kk * QS_STRIDE + tx * 4 + 2];
            float b3 = Ks[kk * QS_STRIDE + tx * 4 + 3];
            sacc[0][0] = fmaf(a0,b0,sacc[0][0]); sacc[0][1] = fmaf(a0,b1,sacc[0][1]);
            sacc[0][2] = fmaf(a0,b2,sacc[0][2]); sacc[0][3] = fmaf(a0,b3,sacc[0][3]);
            sacc[1][0] = fmaf(a1,b0,sacc[1][0]); sacc[1][1] = fmaf(a1,b1,sacc[1][1]);
            sacc[1][2] = fmaf(a1,b2,sacc[1][2]); sacc[1][3] = fmaf(a1,b3,sacc[1][3]);
            sacc[2][0] = fmaf(a2,b0,sacc[2][0]); sacc[2][1] = fmaf(a2,b1,sacc[2][1]);
            sacc[2][2] = fmaf(a2,b2,sacc[2][2]); sacc[2][3] = fmaf(a2,b3,sacc[2][3]);
            sacc[3][0] = fmaf(a3,b0,sacc[3][0]); sacc[3][1] = fmaf(a3,b1,sacc[3][1]);
            sacc[3][2] = fmaf(a3,b2,sacc[3][2]); sacc[3][3] = fmaf(a3,b3,sacc[3][3]);
        }
        int qg0 = bi * 64 + ty * 4;
        int kg0 = j  * 64 + tx * 4;
        #pragma unroll
        for (int r = 0; r < 4; r++)
            #pragma unroll
            for (int c = 0; c < 4; c++) {
                float v = sacc[r][c] * scale;
                if (j == bi && (kg0 + c) > (qg0 + r)) v = -1e30f;
                Ps[(ty * 4 + r) * PS_STRIDE + tx * 4 + c] = v;
            }
        __syncthreads();

        if (tid < 64) {
            float m_old = mrow[tid];
            float mx = m_old;
            float* pr = &Ps[tid * PS_STRIDE];
            #pragma unroll 8
            for (int c = 0; c < 64; c++) mx = fmaxf(mx, pr[c]);
            float corr = __expf(m_old - mx);
            float sum = 0.f;
            #pragma unroll 8
            for (int c = 0; c < 64; c++) {
                float p = __expf(pr[c] - mx);
                pr[c] = p;
                sum += p;
            }
            lrow[tid] = lrow[tid] * corr + sum;
            mrow[tid] = mx;
            crow[tid] = corr;
        }
        __syncthreads();

        float cr[4];
        #pragma unroll
        for (int r = 0; r < 4; r++) cr[r] = crow[ty * 4 + r];
        #pragma unroll
        for (int r = 0; r < 4; r++)
            #pragma unroll
            for (int d = 0; d < 12; d++) O[r][d] *= cr[r];
        #pragma unroll 2
        for (int kk = 0; kk < 64; kk++) {
            float p0 = Ps[(ty * 4 + 0) * PS_STRIDE + kk];
            float p1 = Ps[(ty * 4 + 1) * PS_STRIDE + kk];
            float p2 = Ps[(ty * 4 + 2) * PS_STRIDE + kk];
            float p3 = Ps[(ty * 4 + 3) * PS_STRIDE + kk];
            float vv[12];
            *(float4*)&vv[0] = *(float4*)&Vs[kk * DH + tx * 12 + 0];
            *(float4*)&vv[4] = *(float4*)&Vs[kk * DH + tx * 12 + 4];
            *(float4*)&vv[8] = *(float4*)&Vs[kk * DH + tx * 12 + 8];
            #pragma unroll
            for (int d = 0; d < 12; d++) {
                O[0][d] = fmaf(p0, vv[d], O[0][d]);
                O[1][d] = fmaf(p1, vv[d], O[1][d]);
                O[2][d] = fmaf(p2, vv[d], O[2][d]);
                O[3][d] = fmaf(p3, vv[d], O[3][d]);
            }
        }
    }

    float* ob = attn + ((size_t)(b * SEQ + bi * 64)) * DM + h * DH;
    #pragma unroll
    for (int r = 0; r < 4; r++) {
        float linv = 1.0f / lrow[ty * 4 + r];
        #pragma unroll
        for (int d = 0; d < 12; d++)
            ob[(size_t)(ty * 4 + r) * DM + tx * 12 + d] = O[r][d] * linv;
    }
}

// ---------------- launch -----------------------------------------------
extern "C" void kernel_launch(void* const* d_in, const int* in_sizes, int n_in,
                              void* d_out, int out_size)
{
    const float* x   = (const float*)d_in[0];
    const float* W1  = (const float*)d_in[2];
    const float* b1  = (const float*)d_in[3];
    const float* W3  = (const float*)d_in[4];
    const float* b3  = (const float*)d_in[5];
    const float* W2  = (const float*)d_in[6];
    const float* b2  = (const float*)d_in[7];
    const float* W4  = (const float*)d_in[8];
    const float* b4  = (const float*)d_in[9];
    const float* g1  = (const float*)d_in[10];
    const float* be1 = (const float*)d_in[11];
    const float* g2  = (const float*)d_in[12];
    const float* be2 = (const float*)d_in[13];
    float* out = (float*)d_out;

    float *xn, *qkv, *att, *x1, *xn2, *hbuf;
    cudaGetSymbolAddress((void**)&xn,   g_xn);
    cudaGetSymbolAddress((void**)&qkv,  g_qkv);
    cudaGetSymbolAddress((void**)&att,  g_att);
    cudaGetSymbolAddress((void**)&x1,   g_x1);
    cudaGetSymbolAddress((void**)&xn2,  g_xn2);
    cudaGetSymbolAddress((void**)&hbuf, g_h);

    cudaFuncSetAttribute(attention_kernel,
                         cudaFuncAttributeMaxDynamicSharedMemorySize, ATT_SMEM_BYTES);

    // 1) LN1
    ln_kernel<<<ROWS, 256>>>(x, g1, be1, xn);

    // 2) qkv = xn @ W1 + b1
    bgemm_kernel<false><<<dim3(D3/128, ROWS/128), 256>>>(xn, W1, b1, nullptr, qkv, ROWS, D3, DM);

    // 3) present output
    if ((size_t)out_size >= XOUT_ELEMS + PRES_ELEMS) {
        present_kernel<<<(int)((PRES_ELEMS + 255) / 256), 256>>>(qkv, out + XOUT_ELEMS);
    }

    // 4) attention
    attention_kernel<<<dim3(SEQ/64, NH, BS), 256, ATT_SMEM_BYTES>>>(qkv, att);

    // 5) x1 = att @ W3 + b3 + x
    bgemm_kernel<false><<<dim3(DM/128, ROWS/128), 256>>>(att, W3, b3, x, x1, ROWS, DM, DM);

    // 6) LN2
    ln_kernel<<<ROWS, 256>>>(x1, g2, be2, xn2);

    // 7) h = gelu(xn2 @ W2 + b2)
    bgemm_kernel<true><<<dim3(D4/128, ROWS/128), 256>>>(xn2, W2, b2, nullptr, hbuf, ROWS, D4, DM);

    // 8) out = h @ W4 + b4 + x1
    bgemm_kernel<false><<<dim3(DM/128, ROWS/128), 256>>>(hbuf, W4, b4, x1, out, ROWS, DM, D4);
}

// round 3
// speedup vs baseline: 1.9116x; 1.2239x over previous
#include <cuda_runtime.h>
#include <cuda_bf16.h>
#include <math.h>

// ---------------- problem constants ----------------
#define BS   8
#define SEQ  1024
#define DM   768
#define NH   4
#define DH   192
#define ROWS (BS*SEQ)          // 8192
#define D3   (3*DM)            // 2304
#define D4   (4*DM)            // 3072

#define XOUT_ELEMS   ((size_t)ROWS*DM)
#define PRES_ELEMS   ((size_t)BS*2*NH*SEQ*DH)

// ---------------- scratch (device globals) ---------------------------------
__device__ float g_xn [ROWS*DM];
__device__ float g_qkv[(size_t)ROWS*D3];
__device__ float g_att[ROWS*DM];
__device__ float g_x1 [ROWS*DM];
__device__ float g_xn2[ROWS*DM];
__device__ float g_h  [(size_t)ROWS*D4];

// ---------------- LayerNorm -------------------------------------------------
__global__ __launch_bounds__(256) void ln_kernel(
    const float* __restrict__ x, const float* __restrict__ gamma,
    const float* __restrict__ beta, float* __restrict__ out)
{
    int row = blockIdx.x;
    int tid = threadIdx.x;
    const float* xr = x + (size_t)row * DM;
    float v0 = xr[tid], v1 = xr[tid + 256], v2 = xr[tid + 512];
    float s  = v0 + v1 + v2;
    float sq = v0*v0 + v1*v1 + v2*v2;
    #pragma unroll
    for (int o = 16; o > 0; o >>= 1) {
        s  += __shfl_xor_sync(0xffffffffu, s,  o);
        sq += __shfl_xor_sync(0xffffffffu, sq, o);
    }
    __shared__ float ss[8], ssq[8];
    __shared__ float mu_s, rs_s;
    int w = tid >> 5, l = tid & 31;
    if (l == 0) { ss[w] = s; ssq[w] = sq; }
    __syncthreads();
    if (tid == 0) {
        float S = 0.f, SQ = 0.f;
        #pragma unroll
        for (int i = 0; i < 8; i++) { S += ss[i]; SQ += ssq[i]; }
        float mu = S * (1.0f / DM);
        float var = SQ * (1.0f / DM) - mu * mu;
        mu_s = mu;
        rs_s = rsqrtf(var + 1e-3f);
    }
    __syncthreads();
    float mu = mu_s, rs = rs_s;
    float* orow = out + (size_t)row * DM;
    orow[tid      ] = (v0 - mu) * rs * gamma[tid      ] + beta[tid      ];
    orow[tid + 256] = (v1 - mu) * rs * gamma[tid + 256] + beta[tid + 256];
    orow[tid + 512] = (v2 - mu) * rs * gamma[tid + 512] + beta[tid + 512];
}

// ---------------- GELU ------------------------------------------------------
__device__ __forceinline__ float gelu_tanh_f(float x) {
    float x3 = x * x * x;
    float t  = tanhf(0.7978845608028654f * (x + 0.044715f * x3));
    return 0.5f * x * (1.0f + t);
}

// ---------------- bf16 split + mma helpers ---------------------------------
__device__ __forceinline__ void split2(float x0, float x1, unsigned &hi, unsigned &lo) {
    __nv_bfloat16 h0 = __float2bfloat16_rn(x0);
    __nv_bfloat16 h1 = __float2bfloat16_rn(x1);
    __nv_bfloat16 l0 = __float2bfloat16_rn(x0 - __bfloat162float(h0));
    __nv_bfloat16 l1 = __float2bfloat16_rn(x1 - __bfloat162float(h1));
    hi = ((unsigned)__bfloat16_as_ushort(h1) << 16) | (unsigned)__bfloat16_as_ushort(h0);
    lo = ((unsigned)__bfloat16_as_ushort(l1) << 16) | (unsigned)__bfloat16_as_ushort(l0);
}

__device__ __forceinline__ void mma_bf16(float c[4], const unsigned a[4], const unsigned b[2]) {
    asm volatile(
        "mma.sync.aligned.m16n8k16.row.col.f32.bf16.bf16.f32 "
        "{%0,%1,%2,%3}, {%4,%5,%6,%7}, {%8,%9}, {%0,%1,%2,%3};\n"
        : "+f"(c[0]), "+f"(c[1]), "+f"(c[2]), "+f"(c[3])
        : "r"(a[0]), "r"(a[1]), "r"(a[2]), "r"(a[3]), "r"(b[0]), "r"(b[1]));
}

__device__ __forceinline__ void ldsm_x4_t(unsigned &r0, unsigned &r1, unsigned &r2, unsigned &r3, unsigned saddr) {
    asm volatile("ldmatrix.sync.aligned.m8n8.x4.trans.shared.b16 {%0,%1,%2,%3}, [%4];"
        : "=r"(r0), "=r"(r1), "=r"(r2), "=r"(r3) : "r"(saddr));
}

// ---------------- split-bf16 tensor-core GEMM -------------------------------
#define SST 20

template<bool GELU>
__global__ __launch_bounds__(256) void bgemm_kernel(
    const float* __restrict__ A, const float* __restrict__ B,
    const float* __restrict__ bias, const float* __restrict__ res,
    float* __restrict__ C, int M, int N, int K)
{
    __shared__ unsigned As_hi[128*SST], As_lo[128*SST];
    __shared__ unsigned Bs_hi[128*SST], Bs_lo[128*SST];

    const int tid = threadIdx.x;
    const int w = tid >> 5, l = tid & 31;
    const int wm = w & 1, wn = w >> 1;
    const int gid = l >> 2, tig = l & 3;
    const int bx = blockIdx.x, by = blockIdx.y;

    const float* Ab = A + (size_t)(by * 128) * K;
    const float* Bb = B + bx * 128;

    float acc[4][4][4];
    #pragma unroll
    for (int i = 0; i < 4; i++)
        #pragma unroll
        for (int j = 0; j < 4; j++)
            #pragma unroll
            for (int c = 0; c < 4; c++) acc[i][j][c] = 0.f;

    float4 a_st[4];
    float  b_st[4][4];

    const int ntiles = K >> 5;

    auto load_tile = [&](int k0) {
        #pragma unroll
        for (int i = 0; i < 4; i++) {
            int s = tid + (i << 8);
            int m = s >> 3, kv = s & 7;
            a_st[i] = *reinterpret_cast<const float4*>(Ab + (size_t)m * K + k0 + (kv << 2));
        }
        #pragma unroll
        for (int i = 0; i < 4; i++) {
            int s = tid + (i << 8);
            int n = s & 127, k4 = s >> 7;
            int k = k0 + (k4 << 2);
            const float* bp = Bb + (size_t)k * N + n;
            #pragma unroll
            for (int j = 0; j < 4; j++) b_st[i][j] = bp[(size_t)j * N];
        }
    };

    auto store_tile = [&]() {
        #pragma unroll
        for (int i = 0; i < 4; i++) {
            int s = tid + (i << 8);
            int m = s >> 3, kv = s & 7;
            int kp = kv << 1;
            unsigned h0, l0, h1, l1;
            split2(a_st[i].x, a_st[i].y, h0, l0);
            split2(a_st[i].z, a_st[i].w, h1, l1);
            As_hi[m * SST + kp] = h0; As_hi[m * SST + kp + 1] = h1;
            As_lo[m * SST + kp] = l0; As_lo[m * SST + kp + 1] = l1;
        }
        #pragma unroll
        for (int i = 0; i < 4; i++) {
            int s = tid + (i << 8);
            int n = s & 127, k4 = s >> 7;
            int kp = k4 << 1;
            unsigned h0, l0, h1, l1;
            split2(b_st[i][0], b_st[i][1], h0, l0);
            split2(b_st[i][2], b_st[i][3], h1, l1);
            Bs_hi[n * SST + kp] = h0; Bs_hi[n * SST + kp + 1] = h1;
            Bs_lo[n * SST + kp] = l0; Bs_lo[n * SST + kp + 1] = l1;
        }
    };

    load_tile(0);
    store_tile();
    __syncthreads();

    for (int t = 0; t < ntiles; t++) {
        if (t + 1 < ntiles) load_tile((t + 1) << 5);

        #pragma unroll
        for (int ks = 0; ks < 2; ks++) {
            const int kp0 = ks << 3;
            unsigned ah[4][4], al[4][4], bh[4][2], bl[4][2];
            #pragma unroll
            for (int am = 0; am < 4; am++) {
                int mrow = wm * 64 + am * 16;
                int base0 = (mrow + gid) * SST + kp0 + tig;
                int base1 = (mrow + gid + 8) * SST + kp0 + tig;
                ah[am][0] = As_hi[base0];     ah[am][1] = As_hi[base1];
                ah[am][2] = As_hi[base0 + 4]; ah[am][3] = As_hi[base1 + 4];
                al[am][0] = As_lo[base0];     al[am][1] = As_lo[base1];
                al[am][2] = As_lo[base0 + 4]; al[am][3] = As_lo[base1 + 4];
            }
            #pragma unroll
            for (int an = 0; an < 4; an++) {
                int ncol = wn * 32 + an * 8;
                int base = (ncol + gid) * SST + kp0 + tig;
                bh[an][0] = Bs_hi[base]; bh[an][1] = Bs_hi[base + 4];
                bl[an][0] = Bs_lo[base]; bl[an][1] = Bs_lo[base + 4];
            }
            #pragma unroll
            for (int am = 0; am < 4; am++)
                #pragma unroll
                for (int an = 0; an < 4; an++) {
                    mma_bf16(acc[am][an], ah[am], bh[an]);
                    mma_bf16(acc[am][an], al[am], bh[an]);
                    mma_bf16(acc[am][an], ah[am], bl[an]);
                }
        }
        __syncthreads();
        if (t + 1 < ntiles) store_tile();
        __syncthreads();
    }

    #pragma unroll
    for (int am = 0; am < 4; am++) {
        int m0 = by * 128 + wm * 64 + am * 16;
        int r0 = m0 + gid, r1 = m0 + gid + 8;
        #pragma unroll
        for (int an = 0; an < 4; an++) {
            int n0 = bx * 128 + wn * 32 + an * 8 + 2 * tig;
            float bv0 = bias[n0], bv1 = bias[n0 + 1];
            size_t o0 = (size_t)r0 * N + n0;
            size_t o1 = (size_t)r1 * N + n0;
            float v0 = acc[am][an][0] + bv0;
            float v1 = acc[am][an][1] + bv1;
            float v2 = acc[am][an][2] + bv0;
            float v3 = acc[am][an][3] + bv1;
            if (res) {
                v0 += res[o0]; v1 += res[o0 + 1];
                v2 += res[o1]; v3 += res[o1 + 1];
            }
            if (GELU) {
                v0 = gelu_tanh_f(v0); v1 = gelu_tanh_f(v1);
                v2 = gelu_tanh_f(v2); v3 = gelu_tanh_f(v3);
            }
            *reinterpret_cast<float2*>(C + o0) = make_float2(v0, v1);
            *reinterpret_cast<float2*>(C + o1) = make_float2(v2, v3);
        }
    }
}

// ---------------- present copy ----------------------------------------------
__global__ __launch_bounds__(256) void present_kernel(
    const float* __restrict__ qkv, float* __restrict__ out)
{
    size_t idx = (size_t)blockIdx.x * blockDim.x + threadIdx.x;
    if (idx >= PRES_ELEMS) return;
    int d = (int)(idx % DH); size_t t = idx / DH;
    int s = (int)(t % SEQ);  t /= SEQ;
    int h = (int)(t % NH);   t /= NH;
    int kv = (int)(t % 2);
    int b  = (int)(t / 2);
    out[idx] = qkv[((size_t)(b * SEQ + s)) * D3 + (size_t)(kv + 1) * DM + h * DH + d];
}

// ---------------- tensor-core flash attention (split bf16) ------------------
// block: (q-tile of 64, head, batch). 256 threads, 8 warps.
// scores warp grid: 4 (rows) x 2 (cols of 32).  PV warp grid: 4 x 2 (cols of 96).
#define AQ_ST 100    // u32 stride for 192-dh rows (Q/K hi/lo, V hi/lo)
#define AP_ST 36     // u32 stride for 64-kv rows of P hi/lo
#define PS_ST 66     // f32 stride for score rows

// u32 word counts
#define OFF_QL  6400
#define OFF_KH  12800
#define OFF_KL  19200
#define OFF_VH  25600
#define OFF_VL  32000
#define OFF_PH  38400
#define OFF_PL  (38400+2304)
#define OFF_PS  (38400+4608)           // f32 region starts here (4224 floats)
#define OFF_M   (OFF_PS+4224)
#define ATT2_SMEM_WORDS (OFF_M + 192)
#define ATT2_SMEM_BYTES (ATT2_SMEM_WORDS*4)

__global__ __launch_bounds__(256, 1) void attn_mma_kernel(
    const float* __restrict__ qkv, float* __restrict__ attn)
{
    extern __shared__ unsigned smu[];
    unsigned* Qh = smu;
    unsigned* Ql = smu + OFF_QL;
    unsigned* Kh = smu + OFF_KH;
    unsigned* Kl = smu + OFF_KL;
    unsigned* Vh = smu + OFF_VH;
    unsigned* Vl = smu + OFF_VL;
    unsigned* Ph = smu + OFF_PH;
    unsigned* Pl = smu + OFF_PL;
    float* Ps   = (float*)(smu + OFF_PS);
    float* mrow = (float*)(smu + OFF_M);
    float* lrow = mrow + 64;
    float* crow = lrow + 64;

    const int bi = (int)gridDim.x - 1 - (int)blockIdx.x;  // biggest tiles first
    const int h  = blockIdx.y;
    const int b  = blockIdx.z;
    const int tid = threadIdx.x;
    const int w = tid >> 5, l = tid & 31;
    const int gid = l >> 2, tig = l & 3;
    const int wm = w & 3, wn = w >> 2;

    const float scale = 13.856406460551018f;   // sqrt(192) (faithful bug)

    // ---- load Q tile, split to bf16 hi/lo ----
    const float* qbase = qkv + (size_t)(b * SEQ + bi * 64) * D3 + h * DH;
    for (int t = tid; t < 64 * 48; t += 256) {
        int r = t / 48, c = t % 48;
        float4 v = *reinterpret_cast<const float4*>(qbase + (size_t)r * D3 + c * 4);
        unsigned h0, l0, h1, l1;
        split2(v.x, v.y, h0, l0);
        split2(v.z, v.w, h1, l1);
        Qh[r * AQ_ST + c * 2] = h0; Qh[r * AQ_ST + c * 2 + 1] = h1;
        Ql[r * AQ_ST + c * 2] = l0; Ql[r * AQ_ST + c * 2 + 1] = l1;
    }
    if (tid < 64) { mrow[tid] = -1e30f; lrow[tid] = 0.f; }

    float accO[12][4];
    #pragma unroll
    for (int i = 0; i < 12; i++)
        #pragma unroll
        for (int c = 0; c < 4; c++) accO[i][c] = 0.f;

    // base shared addresses for ldmatrix (per-lane constant parts)
    const unsigned vh_base = (unsigned)__cvta_generic_to_shared(Vh);
    const unsigned vl_base = (unsigned)__cvta_generic_to_shared(Vl);
    const int lm_rwi  = (l & 7) + ((l >> 3) & 1) * 8;   // row within k16
    const int lm_ncol = (l >> 4) * 8;                   // +8 col group

    for (int j = 0; j <= bi; j++) {
        __syncthreads();
        // ---- load K/V tile, split hi/lo ----
        const float* kb = qkv + (size_t)(b * SEQ + j * 64) * D3 + DM + h * DH;
        const float* vb = kb + DM;
        for (int t = tid; t < 64 * 48; t += 256) {
            int r = t / 48, c = t % 48;
            float4 kv4 = *reinterpret_cast<const float4*>(kb + (size_t)r * D3 + c * 4);
            unsigned h0, l0, h1, l1;
            split2(kv4.x, kv4.y, h0, l0);
            split2(kv4.z, kv4.w, h1, l1);
            Kh[r * AQ_ST + c * 2] = h0; Kh[r * AQ_ST + c * 2 + 1] = h1;
            Kl[r * AQ_ST + c * 2] = l0; Kl[r * AQ_ST + c * 2 + 1] = l1;
            float4 vv4 = *reinterpret_cast<const float4*>(vb + (size_t)r * D3 + c * 4);
            split2(vv4.x, vv4.y, h0, l0);
            split2(vv4.z, vv4.w, h1, l1);
            Vh[r * AQ_ST + c * 2] = h0; Vh[r * AQ_ST + c * 2 + 1] = h1;
            Vl[r * AQ_ST + c * 2] = l0; Vl[r * AQ_ST + c * 2 + 1] = l1;
        }
        __syncthreads();

        // ---- scores S = Q K^T (3-pass split) ----
        float accS[4][4];
        #pragma unroll
        for (int i = 0; i < 4; i++)
            #pragma unroll
            for (int c = 0; c < 4; c++) accS[i][c] = 0.f;

        #pragma unroll
        for (int ks = 0; ks < 12; ks++) {
            int kp = ks * 8;
            unsigned ah[4], al[4];
            int a0 = (wm * 16 + gid) * AQ_ST + kp + tig;
            int a1 = a0 + 8 * AQ_ST;
            ah[0] = Qh[a0]; ah[1] = Qh[a1]; ah[2] = Qh[a0 + 4]; ah[3] = Qh[a1 + 4];
            al[0] = Ql[a0]; al[1] = Ql[a1]; al[2] = Ql[a0 + 4]; al[3] = Ql[a1 + 4];
            #pragma unroll
            for (int nt = 0; nt < 4; nt++) {
                int bb = (wn * 32 + nt * 8 + gid) * AQ_ST + kp + tig;
                unsigned bh[2], bl2[2];
                bh[0]  = Kh[bb]; bh[1]  = Kh[bb + 4];
                bl2[0] = Kl[bb]; bl2[1] = Kl[bb + 4];
                mma_bf16(accS[nt], ah, bh);
                mma_bf16(accS[nt], al, bh);
                mma_bf16(accS[nt], ah, bl2);
            }
        }
        // epilogue: scale + causal mask -> Ps
        {
            int rl0 = wm * 16 + gid;
            int rl1 = rl0 + 8;
            #pragma unroll
            for (int nt = 0; nt < 4; nt++) {
                int cl = wn * 32 + nt * 8 + 2 * tig;
                float v0 = accS[nt][0] * scale;
                float v1 = accS[nt][1] * scale;
                float v2 = accS[nt][2] * scale;
                float v3 = accS[nt][3] * scale;
                if (j == bi) {
                    if (cl     > rl0) v0 = -1e30f;
                    if (cl + 1 > rl0) v1 = -1e30f;
                    if (cl     > rl1) v2 = -1e30f;
                    if (cl + 1 > rl1) v3 = -1e30f;
                }
                Ps[rl0 * PS_ST + cl]     = v0;
                Ps[rl0 * PS_ST + cl + 1] = v1;
                Ps[rl1 * PS_ST + cl]     = v2;
                Ps[rl1 * PS_ST + cl + 1] = v3;
            }
        }
        __syncthreads();

        // ---- online softmax: 4 threads per row ----
        {
            int r = tid >> 2, sb = tid & 3;
            const float* pr = Ps + r * PS_ST + sb * 16;
            float pv[16];
            float mx = -1e30f;
            #pragma unroll
            for (int i = 0; i < 16; i++) { pv[i] = pr[i]; mx = fmaxf(mx, pv[i]); }
            mx = fmaxf(mx, __shfl_xor_sync(0xffffffffu, mx, 1));
            mx = fmaxf(mx, __shfl_xor_sync(0xffffffffu, mx, 2));
            float mo = mrow[r];
            float mn = fmaxf(mo, mx);
            float sum = 0.f;
            #pragma unroll
            for (int i = 0; i < 8; i++) {
                float p0 = __expf(pv[2 * i]     - mn);
                float p1 = __expf(pv[2 * i + 1] - mn);
                sum += p0 + p1;
                unsigned hw, lw;
                split2(p0, p1, hw, lw);
                Ph[r * AP_ST + sb * 8 + i] = hw;
                Pl[r * AP_ST + sb * 8 + i] = lw;
            }
            sum += __shfl_xor_sync(0xffffffffu, sum, 1);
            sum += __shfl_xor_sync(0xffffffffu, sum, 2);
            if (sb == 0) {
                float corr = __expf(mo - mn);
                lrow[r] = lrow[r] * corr + sum;
                mrow[r] = mn;
                crow[r] = corr;
            }
        }
        __syncthreads();

        // ---- O = O*corr + P V (3-pass split) ----
        float c0 = crow[wm * 16 + gid];
        float c1 = crow[wm * 16 + gid + 8];
        #pragma unroll
        for (int nt = 0; nt < 12; nt++) {
            accO[nt][0] *= c0; accO[nt][1] *= c0;
            accO[nt][2] *= c1; accO[nt][3] *= c1;
        }
        #pragma unroll
        for (int ks = 0; ks < 4; ks++) {
            int kp = ks * 8;
            unsigned ah[4], al[4];
            int a0 = (wm * 16 + gid) * AP_ST + kp + tig;
            int a1 = a0 + 8 * AP_ST;
            ah[0] = Ph[a0]; ah[1] = Ph[a1]; ah[2] = Ph[a0 + 4]; ah[3] = Ph[a1 + 4];
            al[0] = Pl[a0]; al[1] = Pl[a1]; al[2] = Pl[a0 + 4]; al[3] = Pl[a1 + 4];
            unsigned rowoff = (unsigned)((ks * 16 + lm_rwi) * AQ_ST) * 4u;
            #pragma unroll
            for (int ntp = 0; ntp < 6; ntp++) {
                int n0 = wn * 96 + ntp * 16;
                unsigned coloff = (unsigned)((n0 >> 1) + lm_ncol / 2) * 4u;
                unsigned bh0, bh1, bh2, bh3, bl0, bl1, bl2, bl3;
                ldsm_x4_t(bh0, bh1, bh2, bh3, vh_base + rowoff + coloff);
                ldsm_x4_t(bl0, bl1, bl2, bl3, vl_base + rowoff + coloff);
                unsigned bfh[2], bfl[2];
                bfh[0] = bh0; bfh[1] = bh1; bfl[0] = bl0; bfl[1] = bl1;
                mma_bf16(accO[2 * ntp], ah, bfh);
                mma_bf16(accO[2 * ntp], al, bfh);
                mma_bf16(accO[2 * ntp], ah, bfl);
                bfh[0] = bh2; bfh[1] = bh3; bfl[0] = bl2; bfl[1] = bl3;
                mma_bf16(accO[2 * ntp + 1], ah, bfh);
                mma_bf16(accO[2 * ntp + 1], al, bfh);
                mma_bf16(accO[2 * ntp + 1], ah, bfl);
            }
        }
    }

    // ---- final normalize + write ----
    float li0 = 1.0f / lrow[wm * 16 + gid];
    float li1 = 1.0f / lrow[wm * 16 + gid + 8];
    int row0 = b * SEQ + bi * 64 + wm * 16 + gid;
    #pragma unroll
    for (int nt = 0; nt < 12; nt++) {
        int col = h * DH + wn * 96 + nt * 8 + 2 * tig;
        *reinterpret_cast<float2*>(attn + (size_t)row0 * DM + col) =
            make_float2(accO[nt][0] * li0, accO[nt][1] * li0);
        *reinterpret_cast<float2*>(attn + (size_t)(row0 + 8) * DM + col) =
            make_float2(accO[nt][2] * li1, accO[nt][3] * li1);
    }
}

// ---------------- launch -----------------------------------------------
extern "C" void kernel_launch(void* const* d_in, const int* in_sizes, int n_in,
                              void* d_out, int out_size)
{
    const float* x   = (const float*)d_in[0];
    const float* W1  = (const float*)d_in[2];
    const float* b1  = (const float*)d_in[3];
    const float* W3  = (const float*)d_in[4];
    const float* b3  = (const float*)d_in[5];
    const float* W2  = (const float*)d_in[6];
    const float* b2  = (const float*)d_in[7];
    const float* W4  = (const float*)d_in[8];
    const float* b4  = (const float*)d_in[9];
    const float* g1  = (const float*)d_in[10];
    const float* be1 = (const float*)d_in[11];
    const float* g2  = (const float*)d_in[12];
    const float* be2 = (const float*)d_in[13];
    float* out = (float*)d_out;

    float *xn, *qkv, *att, *x1, *xn2, *hbuf;
    cudaGetSymbolAddress((void**)&xn,   g_xn);
    cudaGetSymbolAddress((void**)&qkv,  g_qkv);
    cudaGetSymbolAddress((void**)&att,  g_att);
    cudaGetSymbolAddress((void**)&x1,   g_x1);
    cudaGetSymbolAddress((void**)&xn2,  g_xn2);
    cudaGetSymbolAddress((void**)&hbuf, g_h);

    cudaFuncSetAttribute(attn_mma_kernel,
                         cudaFuncAttributeMaxDynamicSharedMemorySize, ATT2_SMEM_BYTES);

    // 1) LN1
    ln_kernel<<<ROWS, 256>>>(x, g1, be1, xn);

    // 2) qkv = xn @ W1 + b1
    bgemm_kernel<false><<<dim3(D3/128, ROWS/128), 256>>>(xn, W1, b1, nullptr, qkv, ROWS, D3, DM);

    // 3) present output
    if ((size_t)out_size >= XOUT_ELEMS + PRES_ELEMS) {
        present_kernel<<<(int)((PRES_ELEMS + 255) / 256), 256>>>(qkv, out + XOUT_ELEMS);
    }

    // 4) attention (tensor core, split bf16)
    attn_mma_kernel<<<dim3(SEQ/64, NH, BS), 256, ATT2_SMEM_BYTES>>>(qkv, att);

    // 5) x1 = att @ W3 + b3 + x
    bgemm_kernel<false><<<dim3(DM/128, ROWS/128), 256>>>(att, W3, b3, x, x1, ROWS, DM, DM);

    // 6) LN2
    ln_kernel<<<ROWS, 256>>>(x1, g2, be2, xn2);

    // 7) h = gelu(xn2 @ W2 + b2)
    bgemm_kernel<true><<<dim3(D4/128, ROWS/128), 256>>>(xn2, W2, b2, nullptr, hbuf, ROWS, D4, DM);

    // 8) out = h @ W4 + b4 + x1
    bgemm_kernel<false><<<dim3(DM/128, ROWS/128), 256>>>(hbuf, W4, b4, x1, out, ROWS, DM, D4);
}

// round 4
// speedup vs baseline: 2.5789x; 1.3491x over previous
#include <cuda_runtime.h>
#include <cuda_bf16.h>
#include <math.h>

// ---------------- problem constants ----------------
#define BS   8
#define SEQ  1024
#define DM   768
#define NH   4
#define DH   192
#define ROWS (BS*SEQ)          // 8192
#define D3   (3*DM)            // 2304
#define D4   (4*DM)            // 3072

#define XOUT_ELEMS   ((size_t)ROWS*DM)
#define PRES_ELEMS   ((size_t)BS*2*NH*SEQ*DH)

// ---------------- scratch (device globals) ---------------------------------
__device__ __align__(256) float g_qkv[(size_t)ROWS*D3];
__device__ __align__(256) float g_x1 [ROWS*DM];

__device__ __align__(256) __nv_bfloat16 g_xnh [ROWS*DM],  g_xnl [ROWS*DM];
__device__ __align__(256) __nv_bfloat16 g_atth[ROWS*DM],  g_attl[ROWS*DM];
__device__ __align__(256) __nv_bfloat16 g_xn2h[ROWS*DM],  g_xn2l[ROWS*DM];
__device__ __align__(256) __nv_bfloat16 g_hh[(size_t)ROWS*D4], g_hl[(size_t)ROWS*D4];

// transposed split weights: [N][K]
__device__ __align__(256) __nv_bfloat16 g_w1h[(size_t)D3*DM], g_w1l[(size_t)D3*DM];
__device__ __align__(256) __nv_bfloat16 g_w3h[(size_t)DM*DM], g_w3l[(size_t)DM*DM];
__device__ __align__(256) __nv_bfloat16 g_w2h[(size_t)D4*DM], g_w2l[(size_t)D4*DM];
__device__ __align__(256) __nv_bfloat16 g_w4h[(size_t)DM*D4], g_w4l[(size_t)DM*D4];

// ---------------- helpers ---------------------------------------------------
__device__ __forceinline__ void split2(float x0, float x1, unsigned &hi, unsigned &lo) {
    __nv_bfloat16 h0 = __float2bfloat16_rn(x0);
    __nv_bfloat16 h1 = __float2bfloat16_rn(x1);
    __nv_bfloat16 l0 = __float2bfloat16_rn(x0 - __bfloat162float(h0));
    __nv_bfloat16 l1 = __float2bfloat16_rn(x1 - __bfloat162float(h1));
    hi = ((unsigned)__bfloat16_as_ushort(h1) << 16) | (unsigned)__bfloat16_as_ushort(h0);
    lo = ((unsigned)__bfloat16_as_ushort(l1) << 16) | (unsigned)__bfloat16_as_ushort(l0);
}

__device__ __forceinline__ void mma_bf16(float c[4], const unsigned a[4], const unsigned b[2]) {
    asm volatile(
        "mma.sync.aligned.m16n8k16.row.col.f32.bf16.bf16.f32 "
        "{%0,%1,%2,%3}, {%4,%5,%6,%7}, {%8,%9}, {%0,%1,%2,%3};\n"
        : "+f"(c[0]), "+f"(c[1]), "+f"(c[2]), "+f"(c[3])
        : "r"(a[0]), "r"(a[1]), "r"(a[2]), "r"(a[3]), "r"(b[0]), "r"(b[1]));
}

__device__ __forceinline__ void ldsm_x4(unsigned r[4], unsigned addr) {
    asm volatile("ldmatrix.sync.aligned.m8n8.x4.shared.b16 {%0,%1,%2,%3}, [%4];"
        : "=r"(r[0]), "=r"(r[1]), "=r"(r[2]), "=r"(r[3]) : "r"(addr));
}

__device__ __forceinline__ void ldsm_x4_t(unsigned &r0, unsigned &r1, unsigned &r2, unsigned &r3, unsigned saddr) {
    asm volatile("ldmatrix.sync.aligned.m8n8.x4.trans.shared.b16 {%0,%1,%2,%3}, [%4];"
        : "=r"(r0), "=r"(r1), "=r"(r2), "=r"(r3) : "r"(saddr));
}

#define CP16(dst, src) asm volatile("cp.async.cg.shared.global [%0], [%1], 16;\n" :: "r"(dst), "l"(src))

__device__ __forceinline__ float gelu_tanh_f(float x) {
    float x3 = x * x * x;
    float t  = tanhf(0.7978845608028654f * (x + 0.044715f * x3));
    return 0.5f * x * (1.0f + t);
}

// ---------------- weight transpose + split: W[K][N] -> Wt_hi/lo[N][K] ------
__global__ __launch_bounds__(256) void wsplit_kernel(
    const float* __restrict__ W, __nv_bfloat16* __restrict__ Th,
    __nv_bfloat16* __restrict__ Tl, int K, int N)
{
    __shared__ float t[32][33];
    int n0 = blockIdx.x * 32, k0 = blockIdx.y * 32;
    int tx = threadIdx.x & 31, ty = threadIdx.x >> 5;
    #pragma unroll
    for (int j = 0; j < 4; j++)
        t[ty + 8 * j][tx] = W[(size_t)(k0 + ty + 8 * j) * N + n0 + tx];
    __syncthreads();
    #pragma unroll
    for (int j = 0; j < 4; j++) {
        float v = t[tx][ty + 8 * j];
        __nv_bfloat16 hi = __float2bfloat16_rn(v);
        size_t o = (size_t)(n0 + ty + 8 * j) * K + k0 + tx;
        Th[o] = hi;
        Tl[o] = __float2bfloat16_rn(v - __bfloat162float(hi));
    }
}

// ---------------- LayerNorm, writes split bf16 hi/lo ------------------------
__global__ __launch_bounds__(256) void ln_kernel(
    const float* __restrict__ x, const float* __restrict__ gamma,
    const float* __restrict__ beta,
    __nv_bfloat16* __restrict__ oh, __nv_bfloat16* __restrict__ ol)
{
    int row = blockIdx.x;
    int tid = threadIdx.x;
    const float* xr = x + (size_t)row * DM;
    float v0 = xr[tid], v1 = xr[tid + 256], v2 = xr[tid + 512];
    float s  = v0 + v1 + v2;
    float sq = v0*v0 + v1*v1 + v2*v2;
    #pragma unroll
    for (int o = 16; o > 0; o >>= 1) {
        s  += __shfl_xor_sync(0xffffffffu, s,  o);
        sq += __shfl_xor_sync(0xffffffffu, sq, o);
    }
    __shared__ float ss[8], ssq[8];
    __shared__ float mu_s, rs_s;
    int w = tid >> 5, l = tid & 31;
    if (l == 0) { ss[w] = s; ssq[w] = sq; }
    __syncthreads();
    if (tid == 0) {
        float S = 0.f, SQ = 0.f;
        #pragma unroll
        for (int i = 0; i < 8; i++) { S += ss[i]; SQ += ssq[i]; }
        float mu = S * (1.0f / DM);
        float var = SQ * (1.0f / DM) - mu * mu;
        mu_s = mu;
        rs_s = rsqrtf(var + 1e-3f);
    }
    __syncthreads();
    float mu = mu_s, rs = rs_s;
    size_t ro = (size_t)row * DM;
    #pragma unroll
    for (int q = 0; q < 3; q++) {
        int c = tid + q * 256;
        float v = (q == 0 ? v0 : (q == 1 ? v1 : v2));
        float y = (v - mu) * rs * gamma[c] + beta[c];
        __nv_bfloat16 hi = __float2bfloat16_rn(y);
        oh[ro + c] = hi;
        ol[ro + c] = __float2bfloat16_rn(y - __bfloat162float(hi));
    }
}

// ---------------- split-bf16 GEMM v2: cp.async + ldmatrix -------------------
// A_hi/lo [M][K] bf16, B_hi/lo [N][K] bf16 (pre-transposed).
// Block 128x128, BK=64, 2-stage pipeline, 8 warps (2M x 4N), warp 64x32.
#define SROW 144                    // bytes per smem row (64 bf16 + 16B pad)
#define STG_MAT 18432               // bytes per matrix per stage (128*144)
#define STG_TOT (4*STG_MAT)         // bytes per stage
#define GEMM2_SMEM (2*STG_TOT)      // 147456 bytes

template<bool GELU, bool SPLIT_OUT>
__global__ __launch_bounds__(256, 1) void bgemm2_kernel(
    const __nv_bfloat16* __restrict__ Ah, const __nv_bfloat16* __restrict__ Al,
    const __nv_bfloat16* __restrict__ Bh, const __nv_bfloat16* __restrict__ Bl,
    const float* __restrict__ bias, const float* __restrict__ res,
    float* __restrict__ C, __nv_bfloat16* __restrict__ Ch, __nv_bfloat16* __restrict__ Cl,
    int M, int N, int K)
{
    extern __shared__ unsigned char sm2[];
    const int tid = threadIdx.x;
    const int w = tid >> 5, l = tid & 31;
    const int wm = w & 1, wn = w >> 1;
    const int gid = l >> 2, tig = l & 3;
    const int bx = blockIdx.x, by = blockIdx.y;
    const int T = K >> 6;

    const unsigned smem_base = (unsigned)__cvta_generic_to_shared(sm2);

    const __nv_bfloat16* A0 = Ah + (size_t)(by * 128) * K;
    const __nv_bfloat16* A1 = Al + (size_t)(by * 128) * K;
    const __nv_bfloat16* B0 = Bh + (size_t)(bx * 128) * K;
    const __nv_bfloat16* B1 = Bl + (size_t)(bx * 128) * K;

    // ldmatrix per-lane offsets (bytes)
    const int rl = l & 7, sel = l >> 3;
    const unsigned a_off = (unsigned)((rl + 8 * (sel & 1)) * SROW + 16 * (sel >> 1));
    const unsigned b_off = (unsigned)((rl + 8 * (sel >> 1)) * SROW + 16 * (sel & 1));

    float acc[4][4][4];
    #pragma unroll
    for (int i = 0; i < 4; i++)
        #pragma unroll
        for (int j = 0; j < 4; j++)
            #pragma unroll
            for (int c = 0; c < 4; c++) acc[i][j][c] = 0.f;

    auto issue = [&](int t, int buf) {
        unsigned sb = smem_base + buf * STG_TOT;
        int k0 = t << 6;
        #pragma unroll
        for (int i = 0; i < 4; i++) {
            int idx = tid + (i << 8);
            int m = idx >> 3, c = idx & 7;
            unsigned doff = (unsigned)(m * SROW + c * 16);
            size_t goff = (size_t)m * K + k0 + c * 8;
            CP16(sb + doff,               (const void*)(A0 + goff));
            CP16(sb + STG_MAT + doff,     (const void*)(A1 + goff));
            CP16(sb + 2 * STG_MAT + doff, (const void*)(B0 + goff));
            CP16(sb + 3 * STG_MAT + doff, (const void*)(B1 + goff));
        }
    };

    issue(0, 0);
    asm volatile("cp.async.commit_group;\n" ::);

    for (int t = 0; t < T; t++) {
        if (t + 1 < T) issue(t + 1, (t + 1) & 1);
        asm volatile("cp.async.commit_group;\n" ::);
        asm volatile("cp.async.wait_group 1;\n" ::);
        __syncthreads();

        unsigned sb = smem_base + (t & 1) * STG_TOT;
        #pragma unroll
        for (int ks = 0; ks < 4; ks++) {
            unsigned ah[4][4], al4[4][4], bh[2][4], bl4[2][4];
            #pragma unroll
            for (int am = 0; am < 4; am++) {
                unsigned ad = sb + (unsigned)((wm * 64 + am * 16) * SROW + ks * 32) + a_off;
                ldsm_x4(ah[am], ad);
                ldsm_x4(al4[am], ad + STG_MAT);
            }
            #pragma unroll
            for (int p = 0; p < 2; p++) {
                unsigned bd = sb + 2 * STG_MAT + (unsigned)((wn * 32 + p * 16) * SROW + ks * 32) + b_off;
                ldsm_x4(bh[p], bd);
                ldsm_x4(bl4[p], bd + STG_MAT);
            }
            #pragma unroll
            for (int am = 0; am < 4; am++)
                #pragma unroll
                for (int an = 0; an < 4; an++) {
                    const int p = an >> 1, q = (an & 1) * 2;
                    unsigned bfh[2] = { bh[p][q], bh[p][q + 1] };
                    unsigned bfl[2] = { bl4[p][q], bl4[p][q + 1] };
                    mma_bf16(acc[am][an], ah[am], bfh);
                    mma_bf16(acc[am][an], al4[am], bfh);
                    mma_bf16(acc[am][an], ah[am], bfl);
                }
        }
        __syncthreads();
    }

    // ---- epilogue ----
    #pragma unroll
    for (int am = 0; am < 4; am++) {
        int r0 = by * 128 + wm * 64 + am * 16 + gid;
        int r1 = r0 + 8;
        #pragma unroll
        for (int an = 0; an < 4; an++) {
            int n0 = bx * 128 + wn * 32 + an * 8 + 2 * tig;
            float bv0 = bias[n0], bv1 = bias[n0 + 1];
            size_t o0 = (size_t)r0 * N + n0;
            size_t o1 = (size_t)r1 * N + n0;
            float v0 = acc[am][an][0] + bv0;
            float v1 = acc[am][an][1] + bv1;
            float v2 = acc[am][an][2] + bv0;
            float v3 = acc[am][an][3] + bv1;
            if (res) {
                v0 += res[o0]; v1 += res[o0 + 1];
                v2 += res[o1]; v3 += res[o1 + 1];
            }
            if (GELU) {
                v0 = gelu_tanh_f(v0); v1 = gelu_tanh_f(v1);
                v2 = gelu_tanh_f(v2); v3 = gelu_tanh_f(v3);
            }
            if (SPLIT_OUT) {
                unsigned hw, lw;
                split2(v0, v1, hw, lw);
                *reinterpret_cast<unsigned*>(Ch + o0) = hw;
                *reinterpret_cast<unsigned*>(Cl + o0) = lw;
                split2(v2, v3, hw, lw);
                *reinterpret_cast<unsigned*>(Ch + o1) = hw;
                *reinterpret_cast<unsigned*>(Cl + o1) = lw;
            } else {
                *reinterpret_cast<float2*>(C + o0) = make_float2(v0, v1);
                *reinterpret_cast<float2*>(C + o1) = make_float2(v2, v3);
            }
        }
    }
}

// ---------------- present copy ----------------------------------------------
__global__ __launch_bounds__(256) void present_kernel(
    const float* __restrict__ qkv, float* __restrict__ out)
{
    size_t idx = (size_t)blockIdx.x * blockDim.x + threadIdx.x;
    if (idx >= PRES_ELEMS) return;
    int d = (int)(idx % DH); size_t t = idx / DH;
    int s = (int)(t % SEQ);  t /= SEQ;
    int h = (int)(t % NH);   t /= NH;
    int kv = (int)(t % 2);
    int b  = (int)(t / 2);
    out[idx] = qkv[((size_t)(b * SEQ + s)) * D3 + (size_t)(kv + 1) * DM + h * DH + d];
}

// ---------------- tensor-core flash attention (split bf16) ------------------
#define AQ_ST 100
#define AP_ST 36
#define PS_ST 66

#define OFF_QL  6400
#define OFF_KH  12800
#define OFF_KL  19200
#define OFF_VH  25600
#define OFF_VL  32000
#define OFF_PH  38400
#define OFF_PL  (38400+2304)
#define OFF_PS  (38400+4608)
#define OFF_M   (OFF_PS+4224)
#define ATT2_SMEM_WORDS (OFF_M + 192)
#define ATT2_SMEM_BYTES (ATT2_SMEM_WORDS*4)

__global__ __launch_bounds__(256, 1) void attn_mma_kernel(
    const float* __restrict__ qkv,
    __nv_bfloat16* __restrict__ atth, __nv_bfloat16* __restrict__ attl)
{
    extern __shared__ unsigned smu[];
    unsigned* Qh = smu;
    unsigned* Ql = smu + OFF_QL;
    unsigned* Kh = smu + OFF_KH;
    unsigned* Kl = smu + OFF_KL;
    unsigned* Vh = smu + OFF_VH;
    unsigned* Vl = smu + OFF_VL;
    unsigned* Ph = smu + OFF_PH;
    unsigned* Pl = smu + OFF_PL;
    float* Ps   = (float*)(smu + OFF_PS);
    float* mrow = (float*)(smu + OFF_M);
    float* lrow = mrow + 64;
    float* crow = lrow + 64;

    const int bi = (int)gridDim.x - 1 - (int)blockIdx.x;
    const int h  = blockIdx.y;
    const int b  = blockIdx.z;
    const int tid = threadIdx.x;
    const int w = tid >> 5, l = tid & 31;
    const int gid = l >> 2, tig = l & 3;
    const int wm = w & 3, wn = w >> 2;

    const float scale = 13.856406460551018f;   // sqrt(192) (faithful bug)

    const float* qbase = qkv + (size_t)(b * SEQ + bi * 64) * D3 + h * DH;
    for (int t = tid; t < 64 * 48; t += 256) {
        int r = t / 48, c = t % 48;
        float4 v = *reinterpret_cast<const float4*>(qbase + (size_t)r * D3 + c * 4);
        unsigned h0, l0, h1, l1;
        split2(v.x, v.y, h0, l0);
        split2(v.z, v.w, h1, l1);
        Qh[r * AQ_ST + c * 2] = h0; Qh[r * AQ_ST + c * 2 + 1] = h1;
        Ql[r * AQ_ST + c * 2] = l0; Ql[r * AQ_ST + c * 2 + 1] = l1;
    }
    if (tid < 64) { mrow[tid] = -1e30f; lrow[tid] = 0.f; }

    float accO[12][4];
    #pragma unroll
    for (int i = 0; i < 12; i++)
        #pragma unroll
        for (int c = 0; c < 4; c++) accO[i][c] = 0.f;

    const unsigned vh_base = (unsigned)__cvta_generic_to_shared(Vh);
    const unsigned vl_base = (unsigned)__cvta_generic_to_shared(Vl);
    const int lm_rwi  = (l & 7) + ((l >> 3) & 1) * 8;
    const int lm_ncol = (l >> 4) * 8;

    for (int j = 0; j <= bi; j++) {
        __syncthreads();
        const float* kb = qkv + (size_t)(b * SEQ + j * 64) * D3 + DM + h * DH;
        const float* vb = kb + DM;
        for (int t = tid; t < 64 * 48; t += 256) {
            int r = t / 48, c = t % 48;
            float4 kv4 = *reinterpret_cast<const float4*>(kb + (size_t)r * D3 + c * 4);
            unsigned h0, l0, h1, l1;
            split2(kv4.x, kv4.y, h0, l0);
            split2(kv4.z, kv4.w, h1, l1);
            Kh[r * AQ_ST + c * 2] = h0; Kh[r * AQ_ST + c * 2 + 1] = h1;
            Kl[r * AQ_ST + c * 2] = l0; Kl[r * AQ_ST + c * 2 + 1] = l1;
            float4 vv4 = *reinterpret_cast<const float4*>(vb + (size_t)r * D3 + c * 4);
            split2(vv4.x, vv4.y, h0, l0);
            split2(vv4.z, vv4.w, h1, l1);
            Vh[r * AQ_ST + c * 2] = h0; Vh[r * AQ_ST + c * 2 + 1] = h1;
            Vl[r * AQ_ST + c * 2] = l0; Vl[r * AQ_ST + c * 2 + 1] = l1;
        }
        __syncthreads();

        float accS[4][4];
        #pragma unroll
        for (int i = 0; i < 4; i++)
            #pragma unroll
            for (int c = 0; c < 4; c++) accS[i][c] = 0.f;

        #pragma unroll
        for (int ks = 0; ks < 12; ks++) {
            int kp = ks * 8;
            unsigned ah[4], al[4];
            int a0 = (wm * 16 + gid) * AQ_ST + kp + tig;
            int a1 = a0 + 8 * AQ_ST;
            ah[0] = Qh[a0]; ah[1] = Qh[a1]; ah[2] = Qh[a0 + 4]; ah[3] = Qh[a1 + 4];
            al[0] = Ql[a0]; al[1] = Ql[a1]; al[2] = Ql[a0 + 4]; al[3] = Ql[a1 + 4];
            #pragma unroll
            for (int nt = 0; nt < 4; nt++) {
                int bb = (wn * 32 + nt * 8 + gid) * AQ_ST + kp + tig;
                unsigned bh[2], bl2[2];
                bh[0]  = Kh[bb]; bh[1]  = Kh[bb + 4];
                bl2[0] = Kl[bb]; bl2[1] = Kl[bb + 4];
                mma_bf16(accS[nt], ah, bh);
                mma_bf16(accS[nt], al, bh);
                mma_bf16(accS[nt], ah, bl2);
            }
        }
        {
            int rl0 = wm * 16 + gid;
            int rl1 = rl0 + 8;
            #pragma unroll
            for (int nt = 0; nt < 4; nt++) {
                int cl = wn * 32 + nt * 8 + 2 * tig;
                float v0 = accS[nt][0] * scale;
                float v1 = accS[nt][1] * scale;
                float v2 = accS[nt][2] * scale;
                float v3 = accS[nt][3] * scale;
                if (j == bi) {
                    if (cl     > rl0) v0 = -1e30f;
                    if (cl + 1 > rl0) v1 = -1e30f;
                    if (cl     > rl1) v2 = -1e30f;
                    if (cl + 1 > rl1) v3 = -1e30f;
                }
                Ps[rl0 * PS_ST + cl]     = v0;
                Ps[rl0 * PS_ST + cl + 1] = v1;
                Ps[rl1 * PS_ST + cl]     = v2;
                Ps[rl1 * PS_ST + cl + 1] = v3;
            }
        }
        __syncthreads();

        {
            int r = tid >> 2, sb = tid & 3;
            const float* pr = Ps + r * PS_ST + sb * 16;
            float pv[16];
            float mx = -1e30f;
            #pragma unroll
            for (int i = 0; i < 16; i++) { pv[i] = pr[i]; mx = fmaxf(mx, pv[i]); }
            mx = fmaxf(mx, __shfl_xor_sync(0xffffffffu, mx, 1));
            mx = fmaxf(mx, __shfl_xor_sync(0xffffffffu, mx, 2));
            float mo = mrow[r];
            float mn = fmaxf(mo, mx);
            float sum = 0.f;
            #pragma unroll
            for (int i = 0; i < 8; i++) {
                float p0 = __expf(pv[2 * i]     - mn);
                float p1 = __expf(pv[2 * i + 1] - mn);
                sum += p0 + p1;
                unsigned hw, lw;
                split2(p0, p1, hw, lw);
                Ph[r * AP_ST + sb * 8 + i] = hw;
                Pl[r * AP_ST + sb * 8 + i] = lw;
            }
            sum += __shfl_xor_sync(0xffffffffu, sum, 1);
            sum += __shfl_xor_sync(0xffffffffu, sum, 2);
            if (sb == 0) {
                float corr = __expf(mo - mn);
                lrow[r] = lrow[r] * corr + sum;
                mrow[r] = mn;
                crow[r] = corr;
            }
        }
        __syncthreads();

        float c0 = crow[wm * 16 + gid];
        float c1 = crow[wm * 16 + gid + 8];
        #pragma unroll
        for (int nt = 0; nt < 12; nt++) {
            accO[nt][0] *= c0; accO[nt][1] *= c0;
            accO[nt][2] *= c1; accO[nt][3] *= c1;
        }
        #pragma unroll
        for (int ks = 0; ks < 4; ks++) {
            int kp = ks * 8;
            unsigned ah[4], al[4];
            int a0 = (wm * 16 + gid) * AP_ST + kp + tig;
            int a1 = a0 + 8 * AP_ST;
            ah[0] = Ph[a0]; ah[1] = Ph[a1]; ah[2] = Ph[a0 + 4]; ah[3] = Ph[a1 + 4];
            al[0] = Pl[a0]; al[1] = Pl[a1]; al[2] = Pl[a0 + 4]; al[3] = Pl[a1 + 4];
            unsigned rowoff = (unsigned)((ks * 16 + lm_rwi) * AQ_ST) * 4u;
            #pragma unroll
            for (int ntp = 0; ntp < 6; ntp++) {
                int n0 = wn * 96 + ntp * 16;
                unsigned coloff = (unsigned)((n0 >> 1) + lm_ncol / 2) * 4u;
                unsigned bh0, bh1, bh2, bh3, bl0, bl1, bl2, bl3;
                ldsm_x4_t(bh0, bh1, bh2, bh3, vh_base + rowoff + coloff);
                ldsm_x4_t(bl0, bl1, bl2, bl3, vl_base + rowoff + coloff);
                unsigned bfh[2], bfl[2];
                bfh[0] = bh0; bfh[1] = bh1; bfl[0] = bl0; bfl[1] = bl1;
                mma_bf16(accO[2 * ntp], ah, bfh);
                mma_bf16(accO[2 * ntp], al, bfh);
                mma_bf16(accO[2 * ntp], ah, bfl);
                bfh[0] = bh2; bfh[1] = bh3; bfl[0] = bl2; bfl[1] = bl3;
                mma_bf16(accO[2 * ntp + 1], ah, bfh);
                mma_bf16(accO[2 * ntp + 1], al, bfh);
                mma_bf16(accO[2 * ntp + 1], ah, bfl);
            }
        }
    }

    // final normalize + split write
    float li0 = 1.0f / lrow[wm * 16 + gid];
    float li1 = 1.0f / lrow[wm * 16 + gid + 8];
    int row0 = b * SEQ + bi * 64 + wm * 16 + gid;
    #pragma unroll
    for (int nt = 0; nt < 12; nt++) {
        int col = h * DH + wn * 96 + nt * 8 + 2 * tig;
        size_t o0 = (size_t)row0 * DM + col;
        size_t o1 = (size_t)(row0 + 8) * DM + col;
        unsigned hw, lw;
        split2(accO[nt][0] * li0, accO[nt][1] * li0, hw, lw);
        *reinterpret_cast<unsigned*>(atth + o0) = hw;
        *reinterpret_cast<unsigned*>(attl + o0) = lw;
        split2(accO[nt][2] * li1, accO[nt][3] * li1, hw, lw);
        *reinterpret_cast<unsigned*>(atth + o1) = hw;
        *reinterpret_cast<unsigned*>(attl + o1) = lw;
    }
}

// ---------------- launch -----------------------------------------------
extern "C" void kernel_launch(void* const* d_in, const int* in_sizes, int n_in,
                              void* d_out, int out_size)
{
    const float* x   = (const float*)d_in[0];
    const float* W1  = (const float*)d_in[2];
    const float* b1  = (const float*)d_in[3];
    const float* W3  = (const float*)d_in[4];
    const float* b3  = (const float*)d_in[5];
    const float* W2  = (const float*)d_in[6];
    const float* b2  = (const float*)d_in[7];
    const float* W4  = (const float*)d_in[8];
    const float* b4  = (const float*)d_in[9];
    const float* g1  = (const float*)d_in[10];
    const float* be1 = (const float*)d_in[11];
    const float* g2  = (const float*)d_in[12];
    const float* be2 = (const float*)d_in[13];
    float* out = (float*)d_out;

    float *qkv, *x1;
    cudaGetSymbolAddress((void**)&qkv, g_qkv);
    cudaGetSymbolAddress((void**)&x1,  g_x1);
    __nv_bfloat16 *xnh, *xnl, *atth, *attl, *xn2h, *xn2l, *hh, *hl;
    __nv_bfloat16 *w1h, *w1l, *w3h, *w3l, *w2h, *w2l, *w4h, *w4l;
    cudaGetSymbolAddress((void**)&xnh,  g_xnh);  cudaGetSymbolAddress((void**)&xnl,  g_xnl);
    cudaGetSymbolAddress((void**)&atth, g_atth); cudaGetSymbolAddress((void**)&attl, g_attl);
    cudaGetSymbolAddress((void**)&xn2h, g_xn2h); cudaGetSymbolAddress((void**)&xn2l, g_xn2l);
    cudaGetSymbolAddress((void**)&hh,   g_hh);   cudaGetSymbolAddress((void**)&hl,   g_hl);
    cudaGetSymbolAddress((void**)&w1h,  g_w1h);  cudaGetSymbolAddress((void**)&w1l,  g_w1l);
    cudaGetSymbolAddress((void**)&w3h,  g_w3h);  cudaGetSymbolAddress((void**)&w3l,  g_w3l);
    cudaGetSymbolAddress((void**)&w2h,  g_w2h);  cudaGetSymbolAddress((void**)&w2l,  g_w2l);
    cudaGetSymbolAddress((void**)&w4h,  g_w4h);  cudaGetSymbolAddress((void**)&w4l,  g_w4l);

    cudaFuncSetAttribute(attn_mma_kernel,
                         cudaFuncAttributeMaxDynamicSharedMemorySize, ATT2_SMEM_BYTES);
    cudaFuncSetAttribute(bgemm2_kernel<false,false>,
                         cudaFuncAttributeMaxDynamicSharedMemorySize, GEMM2_SMEM);
    cudaFuncSetAttribute(bgemm2_kernel<true,true>,
                         cudaFuncAttributeMaxDynamicSharedMemorySize, GEMM2_SMEM);

    // 0) weight transpose+split (constant per call, ~25us)
    wsplit_kernel<<<dim3(D3/32, DM/32), 256>>>(W1, w1h, w1l, DM, D3);
    wsplit_kernel<<<dim3(DM/32, DM/32), 256>>>(W3, w3h, w3l, DM, DM);
    wsplit_kernel<<<dim3(D4/32, DM/32), 256>>>(W2, w2h, w2l, DM, D4);
    wsplit_kernel<<<dim3(DM/32, D4/32), 256>>>(W4, w4h, w4l, D4, DM);

    // 1) LN1 -> split
    ln_kernel<<<ROWS, 256>>>(x, g1, be1, xnh, xnl);

    // 2) qkv = xn @ W1 + b1 (float out)
    bgemm2_kernel<false,false><<<dim3(D3/128, ROWS/128), 256, GEMM2_SMEM>>>(
        xnh, xnl, w1h, w1l, b1, nullptr, qkv, nullptr, nullptr, ROWS, D3, DM);

    // 3) present
    if ((size_t)out_size >= XOUT_ELEMS + PRES_ELEMS) {
        present_kernel<<<(int)((PRES_ELEMS + 255) / 256), 256>>>(qkv, out + XOUT_ELEMS);
    }

    // 4) attention -> split att
    attn_mma_kernel<<<dim3(SEQ/64, NH, BS), 256, ATT2_SMEM_BYTES>>>(qkv, atth, attl);

    // 5) x1 = att @ W3 + b3 + x (float out)
    bgemm2_kernel<false,false><<<dim3(DM/128, ROWS/128), 256, GEMM2_SMEM>>>(
        atth, attl, w3h, w3l, b3, x, x1, nullptr, nullptr, ROWS, DM, DM);

    // 6) LN2 -> split
    ln_kernel<<<ROWS, 256>>>(x1, g2, be2, xn2h, xn2l);

    // 7) h = gelu(xn2 @ W2 + b2) -> split out
    bgemm2_kernel<true,true><<<dim3(D4/128, ROWS/128), 256, GEMM2_SMEM>>>(
        xn2h, xn2l, w2h, w2l, b2, nullptr, nullptr, hh, hl, ROWS, D4, DM);

    // 8) out = h @ W4 + b4 + x1 (float out)
    bgemm2_kernel<false,false><<<dim3(DM/128, ROWS/128), 256, GEMM2_SMEM>>>(
        hh, hl, w4h, w4l, b4, x1, out, nullptr, nullptr, ROWS, DM, D4);
}

// round 6
// speedup vs baseline: 2.8748x; 1.1147x over previous
#include <cuda_runtime.h>
#include <cuda_bf16.h>
#include <math.h>

// ---------------- problem constants ----------------
#define BS   8
#define SEQ  1024
#define DM   768
#define NH   4
#define DH   192
#define ROWS (BS*SEQ)          // 8192
#define D3   (3*DM)            // 2304
#define D4   (4*DM)            // 3072

#define XOUT_ELEMS   ((size_t)ROWS*DM)
#define PRES_ELEMS   ((size_t)BS*2*NH*SEQ*DH)

// ---------------- scratch (device globals) ---------------------------------
__device__ __align__(256) float g_x1 [ROWS*DM];

__device__ __align__(256) __nv_bfloat16 g_qkvh[(size_t)ROWS*D3], g_qkvl[(size_t)ROWS*D3];
__device__ __align__(256) __nv_bfloat16 g_xnh [ROWS*DM],  g_xnl [ROWS*DM];
__device__ __align__(256) __nv_bfloat16 g_atth[ROWS*DM],  g_attl[ROWS*DM];
__device__ __align__(256) __nv_bfloat16 g_xn2h[ROWS*DM],  g_xn2l[ROWS*DM];
__device__ __align__(256) __nv_bfloat16 g_hh[(size_t)ROWS*D4], g_hl[(size_t)ROWS*D4];

// transposed split weights: [N][K]
__device__ __align__(256) __nv_bfloat16 g_w1h[(size_t)D3*DM], g_w1l[(size_t)D3*DM];
__device__ __align__(256) __nv_bfloat16 g_w3h[(size_t)DM*DM], g_w3l[(size_t)DM*DM];
__device__ __align__(256) __nv_bfloat16 g_w2h[(size_t)D4*DM], g_w2l[(size_t)D4*DM];
__device__ __align__(256) __nv_bfloat16 g_w4h[(size_t)DM*D4], g_w4l[(size_t)DM*D4];

// ---------------- helpers ---------------------------------------------------
__device__ __forceinline__ void split2(float x0, float x1, unsigned &hi, unsigned &lo) {
    __nv_bfloat16 h0 = __float2bfloat16_rn(x0);
    __nv_bfloat16 h1 = __float2bfloat16_rn(x1);
    __nv_bfloat16 l0 = __float2bfloat16_rn(x0 - __bfloat162float(h0));
    __nv_bfloat16 l1 = __float2bfloat16_rn(x1 - __bfloat162float(h1));
    hi = ((unsigned)__bfloat16_as_ushort(h1) << 16) | (unsigned)__bfloat16_as_ushort(h0);
    lo = ((unsigned)__bfloat16_as_ushort(l1) << 16) | (unsigned)__bfloat16_as_ushort(l0);
}

__device__ __forceinline__ void mma_bf16(float c[4], const unsigned a[4], const unsigned b[2]) {
    asm volatile(
        "mma.sync.aligned.m16n8k16.row.col.f32.bf16.bf16.f32 "
        "{%0,%1,%2,%3}, {%4,%5,%6,%7}, {%8,%9}, {%0,%1,%2,%3};\n"
        : "+f"(c[0]), "+f"(c[1]), "+f"(c[2]), "+f"(c[3])
        : "r"(a[0]), "r"(a[1]), "r"(a[2]), "r"(a[3]), "r"(b[0]), "r"(b[1]));
}

__device__ __forceinline__ void ldsm_x4(unsigned r[4], unsigned addr) {
    asm volatile("ldmatrix.sync.aligned.m8n8.x4.shared.b16 {%0,%1,%2,%3}, [%4];"
        : "=r"(r[0]), "=r"(r[1]), "=r"(r[2]), "=r"(r[3]) : "r"(addr));
}

__device__ __forceinline__ void ldsm_x4_t(unsigned &r0, unsigned &r1, unsigned &r2, unsigned &r3, unsigned saddr) {
    asm volatile("ldmatrix.sync.aligned.m8n8.x4.trans.shared.b16 {%0,%1,%2,%3}, [%4];"
        : "=r"(r0), "=r"(r1), "=r"(r2), "=r"(r3) : "r"(saddr));
}

#define CP16(dst, src) asm volatile("cp.async.cg.shared.global [%0], [%1], 16;\n" :: "r"(dst), "l"(src))
#define CP_COMMIT() asm volatile("cp.async.commit_group;\n" ::)
#define CP_WAIT0()  asm volatile("cp.async.wait_group 0;\n" ::)
#define CP_WAIT1()  asm volatile("cp.async.wait_group 1;\n" ::)

__device__ __forceinline__ float gelu_tanh_f(float x) {
    float x3 = x * x * x;
    float t  = tanhf(0.7978845608028654f * (x + 0.044715f * x3));
    return 0.5f * x * (1.0f + t);
}

// ---------------- weight transpose + split: W[K][N] -> Wt_hi/lo[N][K] ------
__global__ __launch_bounds__(256) void wsplit_kernel(
    const float* __restrict__ W, __nv_bfloat16* __restrict__ Th,
    __nv_bfloat16* __restrict__ Tl, int K, int N)
{
    __shared__ float t[32][33];
    int n0 = blockIdx.x * 32, k0 = blockIdx.y * 32;
    int tx = threadIdx.x & 31, ty = threadIdx.x >> 5;
    #pragma unroll
    for (int j = 0; j < 4; j++)
        t[ty + 8 * j][tx] = W[(size_t)(k0 + ty + 8 * j) * N + n0 + tx];
    __syncthreads();
    #pragma unroll
    for (int j = 0; j < 4; j++) {
        float v = t[tx][ty + 8 * j];
        __nv_bfloat16 hi = __float2bfloat16_rn(v);
        size_t o = (size_t)(n0 + ty + 8 * j) * K + k0 + tx;
        Th[o] = hi;
        Tl[o] = __float2bfloat16_rn(v - __bfloat162float(hi));
    }
}

// ---------------- LayerNorm, writes split bf16 hi/lo ------------------------
__global__ __launch_bounds__(256) void ln_kernel(
    const float* __restrict__ x, const float* __restrict__ gamma,
    const float* __restrict__ beta,
    __nv_bfloat16* __restrict__ oh, __nv_bfloat16* __restrict__ ol)
{
    int row = blockIdx.x;
    int tid = threadIdx.x;
    const float* xr = x + (size_t)row * DM;
    float v0 = xr[tid], v1 = xr[tid + 256], v2 = xr[tid + 512];
    float s  = v0 + v1 + v2;
    float sq = v0*v0 + v1*v1 + v2*v2;
    #pragma unroll
    for (int o = 16; o > 0; o >>= 1) {
        s  += __shfl_xor_sync(0xffffffffu, s,  o);
        sq += __shfl_xor_sync(0xffffffffu, sq, o);
    }
    __shared__ float ss[8], ssq[8];
    __shared__ float mu_s, rs_s;
    int w = tid >> 5, l = tid & 31;
    if (l == 0) { ss[w] = s; ssq[w] = sq; }
    __syncthreads();
    if (tid == 0) {
        float S = 0.f, SQ = 0.f;
        #pragma unroll
        for (int i = 0; i < 8; i++) { S += ss[i]; SQ += ssq[i]; }
        float mu = S * (1.0f / DM);
        float var = SQ * (1.0f / DM) - mu * mu;
        mu_s = mu;
        rs_s = rsqrtf(var + 1e-3f);
    }
    __syncthreads();
    float mu = mu_s, rs = rs_s;
    size_t ro = (size_t)row * DM;
    #pragma unroll
    for (int q = 0; q < 3; q++) {
        int c = tid + q * 256;
        float v = (q == 0 ? v0 : (q == 1 ? v1 : v2));
        float y = (v - mu) * rs * gamma[c] + beta[c];
        __nv_bfloat16 hi = __float2bfloat16_rn(y);
        oh[ro + c] = hi;
        ol[ro + c] = __float2bfloat16_rn(y - __bfloat162float(hi));
    }
}

// ---------------- split-bf16 GEMM v3: BK=32, 2-stage, 2 CTA/SM --------------
// A_hi/lo [M][K], B_hi/lo [N][K] bf16 K-major. Block 128x128, warp 64x32.
// OMODE: 0 = float C, 1 = split Ch/Cl, 2 = split Ch/Cl + fused present write.
#define SROW3 80                     // bytes per smem row (32 bf16 + 16B pad)
#define MAT3  (128*SROW3)            // 10240 B per matrix per stage
#define STG3  (4*MAT3)               // 40960 B per stage
#define GEMM3_SMEM (2*STG3)          // 81920 B

template<bool GELU, int OMODE>
__global__ __launch_bounds__(256, 2) void bgemm3_kernel(
    const __nv_bfloat16* __restrict__ Ah, const __nv_bfloat16* __restrict__ Al,
    const __nv_bfloat16* __restrict__ Bh, const __nv_bfloat16* __restrict__ Bl,
    const float* __restrict__ bias, const float* __restrict__ res,
    float* __restrict__ C, __nv_bfloat16* __restrict__ Ch, __nv_bfloat16* __restrict__ Cl,
    float* __restrict__ pres, int M, int N, int K)
{
    extern __shared__ unsigned char sm3[];
    const int tid = threadIdx.x;
    const int w = tid >> 5, l = tid & 31;
    const int wm = w & 1, wn = w >> 1;
    const int gid = l >> 2, tig = l & 3;
    const int bx = blockIdx.x, by = blockIdx.y;
    const int T = K >> 5;

    const unsigned smem_base = (unsigned)__cvta_generic_to_shared(sm3);

    const __nv_bfloat16* A0 = Ah + (size_t)(by * 128) * K;
    const __nv_bfloat16* A1 = Al + (size_t)(by * 128) * K;
    const __nv_bfloat16* B0 = Bh + (size_t)(bx * 128) * K;
    const __nv_bfloat16* B1 = Bl + (size_t)(bx * 128) * K;

    // ldmatrix per-lane offsets (bytes)
    const int rl = l & 7, sel = l >> 3;
    const unsigned a_off = (unsigned)((rl + 8 * (sel & 1)) * SROW3 + 16 * (sel >> 1));
    const unsigned b_off = (unsigned)((rl + 8 * (sel >> 1)) * SROW3 + 16 * (sel & 1));

    float acc[4][4][4];
    #pragma unroll
    for (int i = 0; i < 4; i++)
        #pragma unroll
        for (int j = 0; j < 4; j++)
            #pragma unroll
            for (int c = 0; c < 4; c++) acc[i][j][c] = 0.f;

    auto issue = [&](int t) {
        unsigned sb = smem_base + (t & 1) * STG3;
        int k0 = t << 5;
        #pragma unroll
        for (int i = 0; i < 2; i++) {
            int chunk = tid + (i << 8);            // 512 chunks per matrix
            int r = chunk >> 2, c = chunk & 3;
            unsigned doff = (unsigned)(r * SROW3 + c * 16);
            size_t goff = (size_t)r * K + k0 + c * 8;
            CP16(sb + doff,            (const void*)(A0 + goff));
            CP16(sb + MAT3 + doff,     (const void*)(A1 + goff));
            CP16(sb + 2 * MAT3 + doff, (const void*)(B0 + goff));
            CP16(sb + 3 * MAT3 + doff, (const void*)(B1 + goff));
        }
        CP_COMMIT();
    };

    issue(0);
    if (T > 1) issue(1);

    for (int t = 0; t < T; t++) {
        if (t + 1 < T) CP_WAIT1(); else CP_WAIT0();
        __syncthreads();

        unsigned sb = smem_base + (t & 1) * STG3;
        #pragma unroll
        for (int ks = 0; ks < 2; ks++) {
            unsigned bh[2][4], bl4[2][4];
            #pragma unroll
            for (int p = 0; p < 2; p++) {
                unsigned bd = sb + 2 * MAT3 + (unsigned)((wn * 32 + p * 16) * SROW3 + ks * 32) + b_off;
                ldsm_x4(bh[p], bd);
                ldsm_x4(bl4[p], bd + MAT3);
            }
            #pragma unroll
            for (int am = 0; am < 4; am++) {
                unsigned ah[4], al4[4];
                unsigned ad = sb + (unsigned)((wm * 64 + am * 16) * SROW3 + ks * 32) + a_off;
                ldsm_x4(ah, ad);
                ldsm_x4(al4, ad + MAT3);
                #pragma unroll
                for (int an = 0; an < 4; an++) {
                    const int p = an >> 1, q = (an & 1) * 2;
                    unsigned bfh[2] = { bh[p][q], bh[p][q + 1] };
                    unsigned bfl[2] = { bl4[p][q], bl4[p][q + 1] };
                    mma_bf16(acc[am][an], ah, bfh);
                    mma_bf16(acc[am][an], al4, bfh);
                    mma_bf16(acc[am][an], ah, bfl);
                }
            }
        }
        __syncthreads();
        if (t + 2 < T) issue(t + 2);
    }

    // ---- epilogue ----
    #pragma unroll
    for (int am = 0; am < 4; am++) {
        int r0 = by * 128 + wm * 64 + am * 16 + gid;
        int r1 = r0 + 8;
        #pragma unroll
        for (int an = 0; an < 4; an++) {
            int n0 = bx * 128 + wn * 32 + an * 8 + 2 * tig;
            float bv0 = bias[n0], bv1 = bias[n0 + 1];
            size_t o0 = (size_t)r0 * N + n0;
            size_t o1 = (size_t)r1 * N + n0;
            float v0 = acc[am][an][0] + bv0;
            float v1 = acc[am][an][1] + bv1;
            float v2 = acc[am][an][2] + bv0;
            float v3 = acc[am][an][3] + bv1;
            if (res) {
                v0 += res[o0]; v1 += res[o0 + 1];
                v2 += res[o1]; v3 += res[o1 + 1];
            }
            if (GELU) {
                v0 = gelu_tanh_f(v0); v1 = gelu_tanh_f(v1);
                v2 = gelu_tanh_f(v2); v3 = gelu_tanh_f(v3);
            }
            if (OMODE == 0) {
                *reinterpret_cast<float2*>(C + o0) = make_float2(v0, v1);
                *reinterpret_cast<float2*>(C + o1) = make_float2(v2, v3);
            } else {
                unsigned hw, lw;
                split2(v0, v1, hw, lw);
                *reinterpret_cast<unsigned*>(Ch + o0) = hw;
                *reinterpret_cast<unsigned*>(Cl + o0) = lw;
                split2(v2, v3, hw, lw);
                *reinterpret_cast<unsigned*>(Ch + o1) = hw;
                *reinterpret_cast<unsigned*>(Cl + o1) = lw;
                if (OMODE == 2 && n0 >= DM) {
                    int kvsel = (n0 >= 2 * DM) ? 1 : 0;
                    int local = n0 - DM - kvsel * DM;
                    int hh = local / DH, dd = local % DH;
                    int b0 = r0 >> 10, s0 = r0 & 1023;
                    int b1 = r1 >> 10, s1 = r1 & 1023;
                    size_t p0 = (((size_t)(b0 * 2 + kvsel) * NH + hh) * SEQ + s0) * DH + dd;
                    size_t p1 = (((size_t)(b1 * 2 + kvsel) * NH + hh) * SEQ + s1) * DH + dd;
                    *reinterpret_cast<float2*>(pres + p0) = make_float2(v0, v1);
                    *reinterpret_cast<float2*>(pres + p1) = make_float2(v2, v3);
                }
            }
        }
    }
}

// ---------------- tensor-core flash attention (split bf16 inputs) -----------
// smem word offsets
#define AQ_ST 100
#define AP_ST 36
#define PS_ST 66

#define OFF_QH  0
#define OFF_QL  6400
#define OFF_KH  12800
#define OFF_KL  19200
#define OFF_VH  25600
#define OFF_VL  32000
#define OFF_PH  38400
#define OFF_PL  (38400+2304)
#define OFF_PS  (38400+4608)
#define OFF_M   (OFF_PS+4224)
#define ATT2_SMEM_WORDS (OFF_M + 192)
#define ATT2_SMEM_BYTES (ATT2_SMEM_WORDS*4)

__global__ __launch_bounds__(256, 1) void attn_mma_kernel(
    const __nv_bfloat16* __restrict__ qkvh, const __nv_bfloat16* __restrict__ qkvl,
    __nv_bfloat16* __restrict__ atth, __nv_bfloat16* __restrict__ attl)
{
    extern __shared__ unsigned smu[];
    unsigned* Ph = smu + OFF_PH;
    unsigned* Pl = smu + OFF_PL;
    float* Ps   = (float*)(smu + OFF_PS);
    float* mrow = (float*)(smu + OFF_M);
    float* lrow = mrow + 64;
    float* crow = lrow + 64;

    const int bi = (int)gridDim.x - 1 - (int)blockIdx.x;  // biggest tiles first
    const int h  = blockIdx.y;
    const int b  = blockIdx.z;
    const int tid = threadIdx.x;
    const int w = tid >> 5, l = tid & 31;
    const int gid = l >> 2, tig = l & 3;
    const int wm = w & 3, wn = w >> 2;

    const float scale = 13.856406460551018f;   // sqrt(192) (faithful bug)

    const unsigned sbase = (unsigned)__cvta_generic_to_shared(smu);

    // ---- Q tile via cp.async (hi + lo) ----
    {
        const size_t row0 = (size_t)(b * SEQ + bi * 64);
        const int qcol = h * DH;
        #pragma unroll
        for (int i = 0; i < 6; i++) {
            int c = tid + (i << 8);             // 1536 chunks
            int r = c / 24, cc = c % 24;
            unsigned doff = (unsigned)((r * AQ_ST + cc * 4) * 4);
            size_t goff = (row0 + r) * D3 + qcol + cc * 8;
            CP16(sbase + OFF_QH * 4 + doff, (const void*)(qkvh + goff));
            CP16(sbase + OFF_QL * 4 + doff, (const void*)(qkvl + goff));
        }
        CP_COMMIT();
    }
    if (tid < 64) { mrow[tid] = -1e30f; lrow[tid] = 0.f; }

    float accO[12][4];
    #pragma unroll
    for (int i = 0; i < 12; i++)
        #pragma unroll
        for (int c = 0; c < 4; c++) accO[i][c] = 0.f;

    const unsigned vh_base = sbase + OFF_VH * 4;
    const unsigned vl_base = sbase + OFF_VL * 4;
    const int lm_rwi  = (l & 7) + ((l >> 3) & 1) * 8;
    const int lm_ncol = (l >> 4) * 8;

    for (int j = 0; j <= bi; j++) {
        __syncthreads();   // previous-iteration consumers done; smem reusable
        // ---- K/V tile via cp.async (hi + lo each) ----
        {
            const size_t row0 = (size_t)(b * SEQ + j * 64);
            const int kcol = DM + h * DH;
            const int vcol = 2 * DM + h * DH;
            #pragma unroll
            for (int i = 0; i < 6; i++) {
                int c = tid + (i << 8);
                int r = c / 24, cc = c % 24;
                unsigned doff = (unsigned)((r * AQ_ST + cc * 4) * 4);
                size_t gk = (row0 + r) * D3 + kcol + cc * 8;
                size_t gv = (row0 + r) * D3 + vcol + cc * 8;
                CP16(sbase + OFF_KH * 4 + doff, (const void*)(qkvh + gk));
                CP16(sbase + OFF_KL * 4 + doff, (const void*)(qkvl + gk));
                CP16(sbase + OFF_VH * 4 + doff, (const void*)(qkvh + gv));
                CP16(sbase + OFF_VL * 4 + doff, (const void*)(qkvl + gv));
            }
            CP_COMMIT();
            CP_WAIT0();
        }
        __syncthreads();

        const unsigned* Qh = smu + OFF_QH;
        const unsigned* Ql = smu + OFF_QL;
        const unsigned* Kh = smu + OFF_KH;
        const unsigned* Kl = smu + OFF_KL;

        // ---- scores S = Q K^T (3-pass split) ----
        float accS[4][4];
        #pragma unroll
        for (int i = 0; i < 4; i++)
            #pragma unroll
            for (int c = 0; c < 4; c++) accS[i][c] = 0.f;

        #pragma unroll
        for (int ks = 0; ks < 12; ks++) {
            int kp = ks * 8;
            unsigned ah[4], al[4];
            int a0 = (wm * 16 + gid) * AQ_ST + kp + tig;
            int a1 = a0 + 8 * AQ_ST;
            ah[0] = Qh[a0]; ah[1] = Qh[a1]; ah[2] = Qh[a0 + 4]; ah[3] = Qh[a1 + 4];
            al[0] = Ql[a0]; al[1] = Ql[a1]; al[2] = Ql[a0 + 4]; al[3] = Ql[a1 + 4];
            #pragma unroll
            for (int nt = 0; nt < 4; nt++) {
                int bb = (wn * 32 + nt * 8 + gid) * AQ_ST + kp + tig;
                unsigned bh[2], bl2[2];
                bh[0]  = Kh[bb]; bh[1]  = Kh[bb + 4];
                bl2[0] = Kl[bb]; bl2[1] = Kl[bb + 4];
                mma_bf16(accS[nt], ah, bh);
                mma_bf16(accS[nt], al, bh);
                mma_bf16(accS[nt], ah, bl2);
            }
        }
        {
            int rl0 = wm * 16 + gid;
            int rl1 = rl0 + 8;
            #pragma unroll
            for (int nt = 0; nt < 4; nt++) {
                int cl = wn * 32 + nt * 8 + 2 * tig;
                float v0 = accS[nt][0] * scale;
                float v1 = accS[nt][1] * scale;
                float v2 = accS[nt][2] * scale;
                float v3 = accS[nt][3] * scale;
                if (j == bi) {
                    if (cl     > rl0) v0 = -1e30f;
                    if (cl + 1 > rl0) v1 = -1e30f;
                    if (cl     > rl1) v2 = -1e30f;
                    if (cl + 1 > rl1) v3 = -1e30f;
                }
                Ps[rl0 * PS_ST + cl]     = v0;
                Ps[rl0 * PS_ST + cl + 1] = v1;
                Ps[rl1 * PS_ST + cl]     = v2;
                Ps[rl1 * PS_ST + cl + 1] = v3;
            }
        }
        __syncthreads();

        // ---- online softmax: 4 threads per row ----
        {
            int r = tid >> 2, sb = tid & 3;
            const float* pr = Ps + r * PS_ST + sb * 16;
            float pv[16];
            float mx = -1e30f;
            #pragma unroll
            for (int i = 0; i < 16; i++) { pv[i] = pr[i]; mx = fmaxf(mx, pv[i]); }
            mx = fmaxf(mx, __shfl_xor_sync(0xffffffffu, mx, 1));
            mx = fmaxf(mx, __shfl_xor_sync(0xffffffffu, mx, 2));
            float mo = mrow[r];
            float mn = fmaxf(mo, mx);
            float sum = 0.f;
            #pragma unroll
            for (int i = 0; i < 8; i++) {
                float p0 = __expf(pv[2 * i]     - mn);
                float p1 = __expf(pv[2 * i + 1] - mn);
                sum += p0 + p1;
                unsigned hw, lw;
                split2(p0, p1, hw, lw);
                Ph[r * AP_ST + sb * 8 + i] = hw;
                Pl[r * AP_ST + sb * 8 + i] = lw;
            }
            sum += __shfl_xor_sync(0xffffffffu, sum, 1);
            sum += __shfl_xor_sync(0xffffffffu, sum, 2);
            if (sb == 0) {
                float corr = __expf(mo - mn);
                lrow[r] = lrow[r] * corr + sum;
                mrow[r] = mn;
                crow[r] = corr;
            }
        }
        __syncthreads();

        // ---- O = O*corr + P V (3-pass split) ----
        float c0 = crow[wm * 16 + gid];
        float c1 = crow[wm * 16 + gid + 8];
        #pragma unroll
        for (int nt = 0; nt < 12; nt++) {
            accO[nt][0] *= c0; accO[nt][1] *= c0;
            accO[nt][2] *= c1; accO[nt][3] *= c1;
        }
        #pragma unroll
        for (int ks = 0; ks < 4; ks++) {
            int kp = ks * 8;
            unsigned ah[4], al[4];
            int a0 = (wm * 16 + gid) * AP_ST + kp + tig;
            int a1 = a0 + 8 * AP_ST;
            ah[0] = Ph[a0]; ah[1] = Ph[a1]; ah[2] = Ph[a0 + 4]; ah[3] = Ph[a1 + 4];
            al[0] = Pl[a0]; al[1] = Pl[a1]; al[2] = Pl[a0 + 4]; al[3] = Pl[a1 + 4];
            unsigned rowoff = (unsigned)((ks * 16 + lm_rwi) * AQ_ST) * 4u;
            #pragma unroll
            for (int ntp = 0; ntp < 6; ntp++) {
                int n0 = wn * 96 + ntp * 16;
                unsigned coloff = (unsigned)((n0 >> 1) + lm_ncol / 2) * 4u;
                unsigned bh0, bh1, bh2, bh3, bl0, bl1, bl2, bl3;
                ldsm_x4_t(bh0, bh1, bh2, bh3, vh_base + rowoff + coloff);
                ldsm_x4_t(bl0, bl1, bl2, bl3, vl_base + rowoff + coloff);
                unsigned bfh[2], bfl[2];
                bfh[0] = bh0; bfh[1] = bh1; bfl[0] = bl0; bfl[1] = bl1;
                mma_bf16(accO[2 * ntp], ah, bfh);
                mma_bf16(accO[2 * ntp], al, bfh);
                mma_bf16(accO[2 * ntp], ah, bfl);
                bfh[0] = bh2; bfh[1] = bh3; bfl[0] = bl2; bfl[1] = bl3;
                mma_bf16(accO[2 * ntp + 1], ah, bfh);
                mma_bf16(accO[2 * ntp + 1], al, bfh);
                mma_bf16(accO[2 * ntp + 1], ah, bfl);
            }
        }
    }

    // ---- final normalize + split write ----
    float li0 = 1.0f / lrow[wm * 16 + gid];
    float li1 = 1.0f / lrow[wm * 16 + gid + 8];
    int row0 = b * SEQ + bi * 64 + wm * 16 + gid;
    #pragma unroll
    for (int nt = 0; nt < 12; nt++) {
        int col = h * DH + wn * 96 + nt * 8 + 2 * tig;
        size_t o0 = (size_t)row0 * DM + col;
        size_t o1 = (size_t)(row0 + 8) * DM + col;
        unsigned hw, lw;
        split2(accO[nt][0] * li0, accO[nt][1] * li0, hw, lw);
        *reinterpret_cast<unsigned*>(atth + o0) = hw;
        *reinterpret_cast<unsigned*>(attl + o0) = lw;
        split2(accO[nt][2] * li1, accO[nt][3] * li1, hw, lw);
        *reinterpret_cast<unsigned*>(atth + o1) = hw;
        *reinterpret_cast<unsigned*>(attl + o1) = lw;
    }
}

// ---------------- launch -----------------------------------------------
extern "C" void kernel_launch(void* const* d_in, const int* in_sizes, int n_in,
                              void* d_out, int out_size)
{
    const float* x   = (const float*)d_in[0];
    const float* W1  = (const float*)d_in[2];
    const float* b1  = (const float*)d_in[3];
    const float* W3  = (const float*)d_in[4];
    const float* b3  = (const float*)d_in[5];
    const float* W2  = (const float*)d_in[6];
    const float* b2  = (const float*)d_in[7];
    const float* W4  = (const float*)d_in[8];
    const float* b4  = (const float*)d_in[9];
    const float* g1  = (const float*)d_in[10];
    const float* be1 = (const float*)d_in[11];
    const float* g2  = (const float*)d_in[12];
    const float* be2 = (const float*)d_in[13];
    float* out = (float*)d_out;

    float *x1;
    cudaGetSymbolAddress((void**)&x1, g_x1);
    __nv_bfloat16 *qkvh, *qkvl, *xnh, *xnl, *atth, *attl, *xn2h, *xn2l, *hh, *hl;
    __nv_bfloat16 *w1h, *w1l, *w3h, *w3l, *w2h, *w2l, *w4h, *w4l;
    cudaGetSymbolAddress((void**)&qkvh, g_qkvh); cudaGetSymbolAddress((void**)&qkvl, g_qkvl);
    cudaGetSymbolAddress((void**)&xnh,  g_xnh);  cudaGetSymbolAddress((void**)&xnl,  g_xnl);
    cudaGetSymbolAddress((void**)&atth, g_atth); cudaGetSymbolAddress((void**)&attl, g_attl);
    cudaGetSymbolAddress((void**)&xn2h, g_xn2h); cudaGetSymbolAddress((void**)&xn2l, g_xn2l);
    cudaGetSymbolAddress((void**)&hh,   g_hh);   cudaGetSymbolAddress((void**)&hl,   g_hl);
    cudaGetSymbolAddress((void**)&w1h,  g_w1h);  cudaGetSymbolAddress((void**)&w1l,  g_w1l);
    cudaGetSymbolAddress((void**)&w3h,  g_w3h);  cudaGetSymbolAddress((void**)&w3l,  g_w3l);
    cudaGetSymbolAddress((void**)&w2h,  g_w2h);  cudaGetSymbolAddress((void**)&w2l,  g_w2l);
    cudaGetSymbolAddress((void**)&w4h,  g_w4h);  cudaGetSymbolAddress((void**)&w4l,  g_w4l);

    cudaFuncSetAttribute(attn_mma_kernel,
                         cudaFuncAttributeMaxDynamicSharedMemorySize, ATT2_SMEM_BYTES);
    cudaFuncSetAttribute(bgemm3_kernel<false,0>,
                         cudaFuncAttributeMaxDynamicSharedMemorySize, GEMM3_SMEM);
    cudaFuncSetAttribute(bgemm3_kernel<false,2>,
                         cudaFuncAttributeMaxDynamicSharedMemorySize, GEMM3_SMEM);
    cudaFuncSetAttribute(bgemm3_kernel<true,1>,
                         cudaFuncAttributeMaxDynamicSharedMemorySize, GEMM3_SMEM);

    float* pres = out + XOUT_ELEMS;
    bool has_present = ((size_t)out_size >= XOUT_ELEMS + PRES_ELEMS);

    // 0) weight transpose+split (constant per call)
    wsplit_kernel<<<dim3(D3/32, DM/32), 256>>>(W1, w1h, w1l, DM, D3);
    wsplit_kernel<<<dim3(DM/32, DM/32), 256>>>(W3, w3h, w3l, DM, DM);
    wsplit_kernel<<<dim3(D4/32, DM/32), 256>>>(W2, w2h, w2l, DM, D4);
    wsplit_kernel<<<dim3(DM/32, D4/32), 256>>>(W4, w4h, w4l, D4, DM);

    // 1) LN1 -> split
    ln_kernel<<<ROWS, 256>>>(x, g1, be1, xnh, xnl);

    // 2) qkv = xn @ W1 + b1 -> split qkv (+ fused present fp32 write)
    if (has_present) {
        bgemm3_kernel<false,2><<<dim3(D3/128, ROWS/128), 256, GEMM3_SMEM>>>(
            xnh, xnl, w1h, w1l, b1, nullptr, nullptr, qkvh, qkvl, pres, ROWS, D3, DM);
    } else {
        bgemm3_kernel<false,1><<<dim3(D3/128, ROWS/128), 256, GEMM3_SMEM>>>(
            xnh, xnl, w1h, w1l, b1, nullptr, nullptr, qkvh, qkvl, nullptr, ROWS, D3, DM);
    }

    // 3) attention (split bf16 in/out)
    attn_mma_kernel<<<dim3(SEQ/64, NH, BS), 256, ATT2_SMEM_BYTES>>>(qkvh, qkvl, atth, attl);

    // 4) x1 = att @ W3 + b3 + x (float out)
    bgemm3_kernel<false,0><<<dim3(DM/128, ROWS/128), 256, GEMM3_SMEM>>>(
        atth, attl, w3h, w3l, b3, x, x1, nullptr, nullptr, nullptr, ROWS, DM, DM);

    // 5) LN2 -> split
    ln_kernel<<<ROWS, 256>>>(x1, g2, be2, xn2h, xn2l);

    // 6) h = gelu(xn2 @ W2 + b2) -> split out
    bgemm3_kernel<true,1><<<dim3(D4/128, ROWS/128), 256, GEMM3_SMEM>>>(
        xn2h, xn2l, w2h, w2l, b2, nullptr, nullptr, hh, hl, nullptr, ROWS, D4, DM);

    // 7) out = h @ W4 + b4 + x1 (float out)
    bgemm3_kernel<false,0><<<dim3(DM/128, ROWS/128), 256, GEMM3_SMEM>>>(
        hh, hl, w4h, w4l, b4, x1, out, nullptr, nullptr, nullptr, ROWS, DM, D4);
}

// round 7
// speedup vs baseline: 2.8965x; 1.0075x over previous
#include <cuda_runtime.h>
#include <cuda_bf16.h>
#include <math.h>

// ---------------- problem constants ----------------
#define BS   8
#define SEQ  1024
#define DM   768
#define NH   4
#define DH   192
#define ROWS (BS*SEQ)          // 8192
#define D3   (3*DM)            // 2304
#define D4   (4*DM)            // 3072

#define XOUT_ELEMS   ((size_t)ROWS*DM)
#define PRES_ELEMS   ((size_t)BS*2*NH*SEQ*DH)

// ---------------- scratch (device globals) ---------------------------------
__device__ __align__(256) float g_x1 [ROWS*DM];

__device__ __align__(256) __nv_bfloat16 g_qkvh[(size_t)ROWS*D3], g_qkvl[(size_t)ROWS*D3];
__device__ __align__(256) __nv_bfloat16 g_xnh [ROWS*DM],  g_xnl [ROWS*DM];
__device__ __align__(256) __nv_bfloat16 g_atth[ROWS*DM],  g_attl[ROWS*DM];
__device__ __align__(256) __nv_bfloat16 g_xn2h[ROWS*DM],  g_xn2l[ROWS*DM];
__device__ __align__(256) __nv_bfloat16 g_hh[(size_t)ROWS*D4], g_hl[(size_t)ROWS*D4];

// transposed split weights: [N][K]
__device__ __align__(256) __nv_bfloat16 g_w1h[(size_t)D3*DM], g_w1l[(size_t)D3*DM];
__device__ __align__(256) __nv_bfloat16 g_w3h[(size_t)DM*DM], g_w3l[(size_t)DM*DM];
__device__ __align__(256) __nv_bfloat16 g_w2h[(size_t)D4*DM], g_w2l[(size_t)D4*DM];
__device__ __align__(256) __nv_bfloat16 g_w4h[(size_t)DM*D4], g_w4l[(size_t)DM*D4];

// ---------------- helpers ---------------------------------------------------
__device__ __forceinline__ void split2(float x0, float x1, unsigned &hi, unsigned &lo) {
    __nv_bfloat16 h0 = __float2bfloat16_rn(x0);
    __nv_bfloat16 h1 = __float2bfloat16_rn(x1);
    __nv_bfloat16 l0 = __float2bfloat16_rn(x0 - __bfloat162float(h0));
    __nv_bfloat16 l1 = __float2bfloat16_rn(x1 - __bfloat162float(h1));
    hi = ((unsigned)__bfloat16_as_ushort(h1) << 16) | (unsigned)__bfloat16_as_ushort(h0);
    lo = ((unsigned)__bfloat16_as_ushort(l1) << 16) | (unsigned)__bfloat16_as_ushort(l0);
}

__device__ __forceinline__ void mma_bf16(float c[4], const unsigned a[4], const unsigned b[2]) {
    asm volatile(
        "mma.sync.aligned.m16n8k16.row.col.f32.bf16.bf16.f32 "
        "{%0,%1,%2,%3}, {%4,%5,%6,%7}, {%8,%9}, {%0,%1,%2,%3};\n"
        : "+f"(c[0]), "+f"(c[1]), "+f"(c[2]), "+f"(c[3])
        : "r"(a[0]), "r"(a[1]), "r"(a[2]), "r"(a[3]), "r"(b[0]), "r"(b[1]));
}

__device__ __forceinline__ void ldsm_x4(unsigned r[4], unsigned addr) {
    asm volatile("ldmatrix.sync.aligned.m8n8.x4.shared.b16 {%0,%1,%2,%3}, [%4];"
        : "=r"(r[0]), "=r"(r[1]), "=r"(r[2]), "=r"(r[3]) : "r"(addr));
}

__device__ __forceinline__ void ldsm_x4_t(unsigned &r0, unsigned &r1, unsigned &r2, unsigned &r3, unsigned saddr) {
    asm volatile("ldmatrix.sync.aligned.m8n8.x4.trans.shared.b16 {%0,%1,%2,%3}, [%4];"
        : "=r"(r0), "=r"(r1), "=r"(r2), "=r"(r3) : "r"(saddr));
}

#define CP16(dst, src) asm volatile("cp.async.cg.shared.global [%0], [%1], 16;\n" :: "r"(dst), "l"(src))
#define CP_COMMIT() asm volatile("cp.async.commit_group;\n" ::)
#define CP_WAIT0()  asm volatile("cp.async.wait_group 0;\n" ::)
#define CP_WAIT1()  asm volatile("cp.async.wait_group 1;\n" ::)

__device__ __forceinline__ float gelu_tanh_f(float x) {
    float x3 = x * x * x;
    float t  = tanhf(0.7978845608028654f * (x + 0.044715f * x3));
    return 0.5f * x * (1.0f + t);
}

// ---------------- weight transpose + split: W[K][N] -> Wt_hi/lo[N][K] ------
__global__ __launch_bounds__(256) void wsplit_kernel(
    const float* __restrict__ W, __nv_bfloat16* __restrict__ Th,
    __nv_bfloat16* __restrict__ Tl, int K, int N)
{
    __shared__ float t[32][33];
    int n0 = blockIdx.x * 32, k0 = blockIdx.y * 32;
    int tx = threadIdx.x & 31, ty = threadIdx.x >> 5;
    #pragma unroll
    for (int j = 0; j < 4; j++)
        t[ty + 8 * j][tx] = W[(size_t)(k0 + ty + 8 * j) * N + n0 + tx];
    __syncthreads();
    #pragma unroll
    for (int j = 0; j < 4; j++) {
        float v = t[tx][ty + 8 * j];
        __nv_bfloat16 hi = __float2bfloat16_rn(v);
        size_t o = (size_t)(n0 + ty + 8 * j) * K + k0 + tx;
        Th[o] = hi;
        Tl[o] = __float2bfloat16_rn(v - __bfloat162float(hi));
    }
}

// ---------------- LayerNorm, writes split bf16 hi/lo ------------------------
__global__ __launch_bounds__(256) void ln_kernel(
    const float* __restrict__ x, const float* __restrict__ gamma,
    const float* __restrict__ beta,
    __nv_bfloat16* __restrict__ oh, __nv_bfloat16* __restrict__ ol)
{
    int row = blockIdx.x;
    int tid = threadIdx.x;
    const float* xr = x + (size_t)row * DM;
    float v0 = xr[tid], v1 = xr[tid + 256], v2 = xr[tid + 512];
    float s  = v0 + v1 + v2;
    float sq = v0*v0 + v1*v1 + v2*v2;
    #pragma unroll
    for (int o = 16; o > 0; o >>= 1) {
        s  += __shfl_xor_sync(0xffffffffu, s,  o);
        sq += __shfl_xor_sync(0xffffffffu, sq, o);
    }
    __shared__ float ss[8], ssq[8];
    __shared__ float mu_s, rs_s;
    int w = tid >> 5, l = tid & 31;
    if (l == 0) { ss[w] = s; ssq[w] = sq; }
    __syncthreads();
    if (tid == 0) {
        float S = 0.f, SQ = 0.f;
        #pragma unroll
        for (int i = 0; i < 8; i++) { S += ss[i]; SQ += ssq[i]; }
        float mu = S * (1.0f / DM);
        float var = SQ * (1.0f / DM) - mu * mu;
        mu_s = mu;
        rs_s = rsqrtf(var + 1e-3f);
    }
    __syncthreads();
    float mu = mu_s, rs = rs_s;
    size_t ro = (size_t)row * DM;
    #pragma unroll
    for (int q = 0; q < 3; q++) {
        int c = tid + q * 256;
        float v = (q == 0 ? v0 : (q == 1 ? v1 : v2));
        float y = (v - mu) * rs * gamma[c] + beta[c];
        __nv_bfloat16 hi = __float2bfloat16_rn(y);
        oh[ro + c] = hi;
        ol[ro + c] = __float2bfloat16_rn(y - __bfloat162float(hi));
    }
}

// ---------------- split-bf16 GEMM v3: BK=32, 2-stage, 2 CTA/SM --------------
#define SROW3 80
#define MAT3  (128*SROW3)
#define STG3  (4*MAT3)
#define GEMM3_SMEM (2*STG3)

template<bool GELU, int OMODE>
__global__ __launch_bounds__(256, 2) void bgemm3_kernel(
    const __nv_bfloat16* __restrict__ Ah, const __nv_bfloat16* __restrict__ Al,
    const __nv_bfloat16* __restrict__ Bh, const __nv_bfloat16* __restrict__ Bl,
    const float* __restrict__ bias, const float* __restrict__ res,
    float* __restrict__ C, __nv_bfloat16* __restrict__ Ch, __nv_bfloat16* __restrict__ Cl,
    float* __restrict__ pres, int M, int N, int K)
{
    extern __shared__ unsigned char sm3[];
    const int tid = threadIdx.x;
    const int w = tid >> 5, l = tid & 31;
    const int wm = w & 1, wn = w >> 1;
    const int gid = l >> 2, tig = l & 3;
    const int bx = blockIdx.x, by = blockIdx.y;
    const int T = K >> 5;

    const unsigned smem_base = (unsigned)__cvta_generic_to_shared(sm3);

    const __nv_bfloat16* A0 = Ah + (size_t)(by * 128) * K;
    const __nv_bfloat16* A1 = Al + (size_t)(by * 128) * K;
    const __nv_bfloat16* B0 = Bh + (size_t)(bx * 128) * K;
    const __nv_bfloat16* B1 = Bl + (size_t)(bx * 128) * K;

    const int rl = l & 7, sel = l >> 3;
    const unsigned a_off = (unsigned)((rl + 8 * (sel & 1)) * SROW3 + 16 * (sel >> 1));
    const unsigned b_off = (unsigned)((rl + 8 * (sel >> 1)) * SROW3 + 16 * (sel & 1));

    float acc[4][4][4];
    #pragma unroll
    for (int i = 0; i < 4; i++)
        #pragma unroll
        for (int j = 0; j < 4; j++)
            #pragma unroll
            for (int c = 0; c < 4; c++) acc[i][j][c] = 0.f;

    auto issue = [&](int t) {
        unsigned sb = smem_base + (t & 1) * STG3;
        int k0 = t << 5;
        #pragma unroll
        for (int i = 0; i < 2; i++) {
            int chunk = tid + (i << 8);
            int r = chunk >> 2, c = chunk & 3;
            unsigned doff = (unsigned)(r * SROW3 + c * 16);
            size_t goff = (size_t)r * K + k0 + c * 8;
            CP16(sb + doff,            (const void*)(A0 + goff));
            CP16(sb + MAT3 + doff,     (const void*)(A1 + goff));
            CP16(sb + 2 * MAT3 + doff, (const void*)(B0 + goff));
            CP16(sb + 3 * MAT3 + doff, (const void*)(B1 + goff));
        }
        CP_COMMIT();
    };

    issue(0);
    if (T > 1) issue(1);

    for (int t = 0; t < T; t++) {
        if (t + 1 < T) CP_WAIT1(); else CP_WAIT0();
        __syncthreads();

        unsigned sb = smem_base + (t & 1) * STG3;
        #pragma unroll
        for (int ks = 0; ks < 2; ks++) {
            unsigned bh[2][4], bl4[2][4];
            #pragma unroll
            for (int p = 0; p < 2; p++) {
                unsigned bd = sb + 2 * MAT3 + (unsigned)((wn * 32 + p * 16) * SROW3 + ks * 32) + b_off;
                ldsm_x4(bh[p], bd);
                ldsm_x4(bl4[p], bd + MAT3);
            }
            #pragma unroll
            for (int am = 0; am < 4; am++) {
                unsigned ah[4], al4[4];
                unsigned ad = sb + (unsigned)((wm * 64 + am * 16) * SROW3 + ks * 32) + a_off;
                ldsm_x4(ah, ad);
                ldsm_x4(al4, ad + MAT3);
                #pragma unroll
                for (int an = 0; an < 4; an++) {
                    const int p = an >> 1, q = (an & 1) * 2;
                    unsigned bfh[2] = { bh[p][q], bh[p][q + 1] };
                    unsigned bfl[2] = { bl4[p][q], bl4[p][q + 1] };
                    mma_bf16(acc[am][an], ah, bfh);
                    mma_bf16(acc[am][an], al4, bfh);
                    mma_bf16(acc[am][an], ah, bfl);
                }
            }
        }
        __syncthreads();
        if (t + 2 < T) issue(t + 2);
    }

    #pragma unroll
    for (int am = 0; am < 4; am++) {
        int r0 = by * 128 + wm * 64 + am * 16 + gid;
        int r1 = r0 + 8;
        #pragma unroll
        for (int an = 0; an < 4; an++) {
            int n0 = bx * 128 + wn * 32 + an * 8 + 2 * tig;
            float bv0 = bias[n0], bv1 = bias[n0 + 1];
            size_t o0 = (size_t)r0 * N + n0;
            size_t o1 = (size_t)r1 * N + n0;
            float v0 = acc[am][an][0] + bv0;
            float v1 = acc[am][an][1] + bv1;
            float v2 = acc[am][an][2] + bv0;
            float v3 = acc[am][an][3] + bv1;
            if (res) {
                v0 += res[o0]; v1 += res[o0 + 1];
                v2 += res[o1]; v3 += res[o1 + 1];
            }
            if (GELU) {
                v0 = gelu_tanh_f(v0); v1 = gelu_tanh_f(v1);
                v2 = gelu_tanh_f(v2); v3 = gelu_tanh_f(v3);
            }
            if (OMODE == 0) {
                *reinterpret_cast<float2*>(C + o0) = make_float2(v0, v1);
                *reinterpret_cast<float2*>(C + o1) = make_float2(v2, v3);
            } else {
                unsigned hw, lw;
                split2(v0, v1, hw, lw);
                *reinterpret_cast<unsigned*>(Ch + o0) = hw;
                *reinterpret_cast<unsigned*>(Cl + o0) = lw;
                split2(v2, v3, hw, lw);
                *reinterpret_cast<unsigned*>(Ch + o1) = hw;
                *reinterpret_cast<unsigned*>(Cl + o1) = lw;
                if (OMODE == 2 && n0 >= DM) {
                    int kvsel = (n0 >= 2 * DM) ? 1 : 0;
                    int local = n0 - DM - kvsel * DM;
                    int hh = local / DH, dd = local % DH;
                    int b0 = r0 >> 10, s0 = r0 & 1023;
                    int b1 = r1 >> 10, s1 = r1 & 1023;
                    size_t p0 = (((size_t)(b0 * 2 + kvsel) * NH + hh) * SEQ + s0) * DH + dd;
                    size_t p1 = (((size_t)(b1 * 2 + kvsel) * NH + hh) * SEQ + s1) * DH + dd;
                    *reinterpret_cast<float2*>(pres + p0) = make_float2(v0, v1);
                    *reinterpret_cast<float2*>(pres + p1) = make_float2(v2, v3);
                }
            }
        }
    }
}

// ---------------- FA2-style attention v3: register softmax ------------------
// q-tile 128 rows/block, 8 warps x 16 rows, KV tiles of 64.
// smem (u32 words): Qh 12800 | Ql 12800 | Kh 6400 | Kl 6400 | Vh 6400 | Vl 6400
#define A3_ST 100
#define A3_QH 0
#define A3_QL 12800
#define A3_KH 25600
#define A3_KL 32000
#define A3_VH 38400
#define A3_VL 44800
#define ATT3_SMEM_BYTES (51200*4)

__global__ __launch_bounds__(256, 1) void attn_v3_kernel(
    const __nv_bfloat16* __restrict__ qkvh, const __nv_bfloat16* __restrict__ qkvl,
    __nv_bfloat16* __restrict__ atth, __nv_bfloat16* __restrict__ attl)
{
    extern __shared__ unsigned smu[];
    const int bi = (int)gridDim.x - 1 - (int)blockIdx.x;   // biggest first
    const int h  = blockIdx.y;
    const int b  = blockIdx.z;
    const int tid = threadIdx.x;
    const int w = tid >> 5, l = tid & 31;
    const int gid = l >> 2, tig = l & 3;

    const float scale = 13.856406460551018f;   // sqrt(192) (faithful bug)
    const unsigned sbase = (unsigned)__cvta_generic_to_shared(smu);

    // ---- load Q tile (128 x 192, hi+lo) ----
    {
        const size_t row0 = (size_t)(b * SEQ + bi * 128);
        const int qcol = h * DH;
        #pragma unroll
        for (int i = 0; i < 12; i++) {
            int c = tid + (i << 8);          // 3072 chunks
            int r = c / 24, cc = c % 24;
            unsigned doff = (unsigned)((r * A3_ST + cc * 4) * 4);
            size_t goff = (row0 + r) * D3 + qcol + cc * 8;
            CP16(sbase + A3_QH * 4 + doff, (const void*)(qkvh + goff));
            CP16(sbase + A3_QL * 4 + doff, (const void*)(qkvl + goff));
        }
        CP_COMMIT();
    }

    float m0 = -1e30f, m1 = -1e30f, l0 = 0.f, l1 = 0.f;
    float accO[24][4];
    #pragma unroll
    for (int i = 0; i < 24; i++)
        #pragma unroll
        for (int c = 0; c < 4; c++) accO[i][c] = 0.f;

    const int lm_rwi  = (l & 7) + ((l >> 3) & 1) * 8;
    const int lm_ncol = (l >> 4) * 8;
    const unsigned vh_base = sbase + A3_VH * 4;
    const unsigned vl_base = sbase + A3_VL * 4;

    const int qg0 = bi * 128 + w * 16 + gid;
    const int qg1 = qg0 + 8;
    const int nkv = 2 * bi + 2;

    for (int j = 0; j < nkv; j++) {
        __syncthreads();   // prev-iter V consumers done
        // ---- load K/V tile (64 x 192, hi+lo each) ----
        {
            const size_t row0 = (size_t)(b * SEQ + j * 64);
            const int kcol = DM + h * DH;
            #pragma unroll
            for (int i = 0; i < 6; i++) {
                int c = tid + (i << 8);      // 1536 chunks
                int r = c / 24, cc = c % 24;
                unsigned doff = (unsigned)((r * A3_ST + cc * 4) * 4);
                size_t gk = (row0 + r) * D3 + kcol + cc * 8;
                size_t gv = gk + DM;
                CP16(sbase + A3_KH * 4 + doff, (const void*)(qkvh + gk));
                CP16(sbase + A3_KL * 4 + doff, (const void*)(qkvl + gk));
                CP16(sbase + A3_VH * 4 + doff, (const void*)(qkvh + gv));
                CP16(sbase + A3_VL * 4 + doff, (const void*)(qkvl + gv));
            }
            CP_COMMIT();
            CP_WAIT0();
        }
        __syncthreads();

        const unsigned* Qh = smu + A3_QH;
        const unsigned* Ql = smu + A3_QL;
        const unsigned* Kh = smu + A3_KH;
        const unsigned* Kl = smu + A3_KL;

        // ---- scores: warp computes 16 x 64 (8 n-tiles) ----
        float accS[8][4];
        #pragma unroll
        for (int i = 0; i < 8; i++)
            #pragma unroll
            for (int c = 0; c < 4; c++) accS[i][c] = 0.f;

        #pragma unroll
        for (int ks = 0; ks < 12; ks++) {
            int kp = ks * 8;
            unsigned ah[4], al[4];
            int a0 = (w * 16 + gid) * A3_ST + kp + tig;
            int a1 = a0 + 8 * A3_ST;
            ah[0] = Qh[a0]; ah[1] = Qh[a1]; ah[2] = Qh[a0 + 4]; ah[3] = Qh[a1 + 4];
            al[0] = Ql[a0]; al[1] = Ql[a1]; al[2] = Ql[a0 + 4]; al[3] = Ql[a1 + 4];
            #pragma unroll
            for (int nt = 0; nt < 8; nt++) {
                int bb = (nt * 8 + gid) * A3_ST + kp + tig;
                unsigned bh[2], bl2[2];
                bh[0]  = Kh[bb]; bh[1]  = Kh[bb + 4];
                bl2[0] = Kl[bb]; bl2[1] = Kl[bb + 4];
                mma_bf16(accS[nt], ah, bh);
                mma_bf16(accS[nt], al, bh);
                mma_bf16(accS[nt], ah, bl2);
            }
        }

        // ---- scale + causal mask + register online softmax ----
        const bool diag = (j >= 2 * bi);
        float mx0 = -1e30f, mx1 = -1e30f;
        #pragma unroll
        for (int nt = 0; nt < 8; nt++) {
            int kg = j * 64 + nt * 8 + 2 * tig;
            float v0 = accS[nt][0] * scale;
            float v1 = accS[nt][1] * scale;
            float v2 = accS[nt][2] * scale;
            float v3 = accS[nt][3] * scale;
            if (diag) {
                if (kg     > qg0) v0 = -1e30f;
                if (kg + 1 > qg0) v1 = -1e30f;
                if (kg     > qg1) v2 = -1e30f;
                if (kg + 1 > qg1) v3 = -1e30f;
            }
            accS[nt][0] = v0; accS[nt][1] = v1;
            accS[nt][2] = v2; accS[nt][3] = v3;
            mx0 = fmaxf(mx0, fmaxf(v0, v1));
            mx1 = fmaxf(mx1, fmaxf(v2, v3));
        }
        mx0 = fmaxf(mx0, __shfl_xor_sync(0xffffffffu, mx0, 1));
        mx0 = fmaxf(mx0, __shfl_xor_sync(0xffffffffu, mx0, 2));
        mx1 = fmaxf(mx1, __shfl_xor_sync(0xffffffffu, mx1, 1));
        mx1 = fmaxf(mx1, __shfl_xor_sync(0xffffffffu, mx1, 2));
        float mn0 = fmaxf(m0, mx0), mn1 = fmaxf(m1, mx1);
        float corr0 = __expf(m0 - mn0), corr1 = __expf(m1 - mn1);

        // exp + pack P into bf16 hi/lo A-fragments (C-frag == A-frag identity)
        unsigned pha[4][4], pla[4][4];
        float sum0 = 0.f, sum1 = 0.f;
        #pragma unroll
        for (int nt = 0; nt < 8; nt++) {
            float p0 = __expf(accS[nt][0] - mn0);
            float p1 = __expf(accS[nt][1] - mn0);
            float p2 = __expf(accS[nt][2] - mn1);
            float p3 = __expf(accS[nt][3] - mn1);
            sum0 += p0 + p1;
            sum1 += p2 + p3;
            const int ks = nt >> 1;
            const int s0 = (nt & 1) * 2;     // a-slot: even nt -> 0,1 ; odd -> 2,3
            split2(p0, p1, pha[ks][s0],     pla[ks][s0]);
            split2(p2, p3, pha[ks][s0 + 1], pla[ks][s0 + 1]);
        }
        sum0 += __shfl_xor_sync(0xffffffffu, sum0, 1);
        sum0 += __shfl_xor_sync(0xffffffffu, sum0, 2);
        sum1 += __shfl_xor_sync(0xffffffffu, sum1, 1);
        sum1 += __shfl_xor_sync(0xffffffffu, sum1, 2);
        l0 = l0 * corr0 + sum0;  m0 = mn0;
        l1 = l1 * corr1 + sum1;  m1 = mn1;

        // ---- O = O*corr + P V ----
        #pragma unroll
        for (int nt = 0; nt < 24; nt++) {
            accO[nt][0] *= corr0; accO[nt][1] *= corr0;
            accO[nt][2] *= corr1; accO[nt][3] *= corr1;
        }
        #pragma unroll
        for (int ks = 0; ks < 4; ks++) {
            unsigned rowoff = (unsigned)((ks * 16 + lm_rwi) * A3_ST) * 4u;
            #pragma unroll
            for (int g = 0; g < 12; g++) {
                unsigned coloff = (unsigned)(g * 8 + lm_ncol / 2) * 4u;
                unsigned bh0, bh1, bh2, bh3, bl0, bl1, bl2, bl3;
                ldsm_x4_t(bh0, bh1, bh2, bh3, vh_base + rowoff + coloff);
                ldsm_x4_t(bl0, bl1, bl2, bl3, vl_base + rowoff + coloff);
                unsigned bfh[2], bfl[2];
                bfh[0] = bh0; bfh[1] = bh1; bfl[0] = bl0; bfl[1] = bl1;
                mma_bf16(accO[2 * g],     pha[ks], bfh);
                mma_bf16(accO[2 * g],     pla[ks], bfh);
                mma_bf16(accO[2 * g],     pha[ks], bfl);
                bfh[0] = bh2; bfh[1] = bh3; bfl[0] = bl2; bfl[1] = bl3;
                mma_bf16(accO[2 * g + 1], pha[ks], bfh);
                mma_bf16(accO[2 * g + 1], pla[ks], bfh);
                mma_bf16(accO[2 * g + 1], pha[ks], bfl);
            }
        }
    }

    // ---- final normalize + split write ----
    float li0 = 1.0f / l0, li1 = 1.0f / l1;
    int row0 = b * SEQ + bi * 128 + w * 16 + gid;
    #pragma unroll
    for (int nt = 0; nt < 24; nt++) {
        int col = h * DH + nt * 8 + 2 * tig;
        size_t o0 = (size_t)row0 * DM + col;
        size_t o1 = (size_t)(row0 + 8) * DM + col;
        unsigned hw, lw;
        split2(accO[nt][0] * li0, accO[nt][1] * li0, hw, lw);
        *reinterpret_cast<unsigned*>(atth + o0) = hw;
        *reinterpret_cast<unsigned*>(attl + o0) = lw;
        split2(accO[nt][2] * li1, accO[nt][3] * li1, hw, lw);
        *reinterpret_cast<unsigned*>(atth + o1) = hw;
        *reinterpret_cast<unsigned*>(attl + o1) = lw;
    }
}

// ---------------- launch -----------------------------------------------
extern "C" void kernel_launch(void* const* d_in, const int* in_sizes, int n_in,
                              void* d_out, int out_size)
{
    const float* x   = (const float*)d_in[0];
    const float* W1  = (const float*)d_in[2];
    const float* b1  = (const float*)d_in[3];
    const float* W3  = (const float*)d_in[4];
    const float* b3  = (const float*)d_in[5];
    const float* W2  = (const float*)d_in[6];
    const float* b2  = (const float*)d_in[7];
    const float* W4  = (const float*)d_in[8];
    const float* b4  = (const float*)d_in[9];
    const float* g1  = (const float*)d_in[10];
    const float* be1 = (const float*)d_in[11];
    const float* g2  = (const float*)d_in[12];
    const float* be2 = (const float*)d_in[13];
    float* out = (float*)d_out;

    float *x1;
    cudaGetSymbolAddress((void**)&x1, g_x1);
    __nv_bfloat16 *qkvh, *qkvl, *xnh, *xnl, *atth, *attl, *xn2h, *xn2l, *hh, *hl;
    __nv_bfloat16 *w1h, *w1l, *w3h, *w3l, *w2h, *w2l, *w4h, *w4l;
    cudaGetSymbolAddress((void**)&qkvh, g_qkvh); cudaGetSymbolAddress((void**)&qkvl, g_qkvl);
    cudaGetSymbolAddress((void**)&xnh,  g_xnh);  cudaGetSymbolAddress((void**)&xnl,  g_xnl);
    cudaGetSymbolAddress((void**)&atth, g_atth); cudaGetSymbolAddress((void**)&attl, g_attl);
    cudaGetSymbolAddress((void**)&xn2h, g_xn2h); cudaGetSymbolAddress((void**)&xn2l, g_xn2l);
    cudaGetSymbolAddress((void**)&hh,   g_hh);   cudaGetSymbolAddress((void**)&hl,   g_hl);
    cudaGetSymbolAddress((void**)&w1h,  g_w1h);  cudaGetSymbolAddress((void**)&w1l,  g_w1l);
    cudaGetSymbolAddress((void**)&w3h,  g_w3h);  cudaGetSymbolAddress((void**)&w3l,  g_w3l);
    cudaGetSymbolAddress((void**)&w2h,  g_w2h);  cudaGetSymbolAddress((void**)&w2l,  g_w2l);
    cudaGetSymbolAddress((void**)&w4h,  g_w4h);  cudaGetSymbolAddress((void**)&w4l,  g_w4l);

    cudaFuncSetAttribute(attn_v3_kernel,
                         cudaFuncAttributeMaxDynamicSharedMemorySize, ATT3_SMEM_BYTES);
    cudaFuncSetAttribute(bgemm3_kernel<false,0>,
                         cudaFuncAttributeMaxDynamicSharedMemorySize, GEMM3_SMEM);
    cudaFuncSetAttribute(bgemm3_kernel<false,1>,
                         cudaFuncAttributeMaxDynamicSharedMemorySize, GEMM3_SMEM);
    cudaFuncSetAttribute(bgemm3_kernel<false,2>,
                         cudaFuncAttributeMaxDynamicSharedMemorySize, GEMM3_SMEM);
    cudaFuncSetAttribute(bgemm3_kernel<true,1>,
                         cudaFuncAttributeMaxDynamicSharedMemorySize, GEMM3_SMEM);

    float* pres = out + XOUT_ELEMS;
    bool has_present = ((size_t)out_size >= XOUT_ELEMS + PRES_ELEMS);

    // 0) weight transpose+split (constant per call)
    wsplit_kernel<<<dim3(D3/32, DM/32), 256>>>(W1, w1h, w1l, DM, D3);
    wsplit_kernel<<<dim3(DM/32, DM/32), 256>>>(W3, w3h, w3l, DM, DM);
    wsplit_kernel<<<dim3(D4/32, DM/32), 256>>>(W2, w2h, w2l, DM, D4);
    wsplit_kernel<<<dim3(DM/32, D4/32), 256>>>(W4, w4h, w4l, D4, DM);

    // 1) LN1 -> split
    ln_kernel<<<ROWS, 256>>>(x, g1, be1, xnh, xnl);

    // 2) qkv = xn @ W1 + b1 -> split qkv (+ fused present fp32 write)
    if (has_present) {
        bgemm3_kernel<false,2><<<dim3(D3/128, ROWS/128), 256, GEMM3_SMEM>>>(
            xnh, xnl, w1h, w1l, b1, nullptr, nullptr, qkvh, qkvl, pres, ROWS, D3, DM);
    } else {
        bgemm3_kernel<false,1><<<dim3(D3/128, ROWS/128), 256, GEMM3_SMEM>>>(
            xnh, xnl, w1h, w1l, b1, nullptr, nullptr, qkvh, qkvl, nullptr, ROWS, D3, DM);
    }

    // 3) attention (FA2-style register softmax)
    attn_v3_kernel<<<dim3(SEQ/128, NH, BS), 256, ATT3_SMEM_BYTES>>>(qkvh, qkvl, atth, attl);

    // 4) x1 = att @ W3 + b3 + x (float out)
    bgemm3_kernel<false,0><<<dim3(DM/128, ROWS/128), 256, GEMM3_SMEM>>>(
        atth, attl, w3h, w3l, b3, x, x1, nullptr, nullptr, nullptr, ROWS, DM, DM);

    // 5) LN2 -> split
    ln_kernel<<<ROWS, 256>>>(x1, g2, be2, xn2h, xn2l);

    // 6) h = gelu(xn2 @ W2 + b2) -> split out
    bgemm3_kernel<true,1><<<dim3(D4/128, ROWS/128), 256, GEMM3_SMEM>>>(
        xn2h, xn2l, w2h, w2l, b2, nullptr, nullptr, hh, hl, nullptr, ROWS, D4, DM);

    // 7) out = h @ W4 + b4 + x1 (float out)
    bgemm3_kernel<false,0><<<dim3(DM/128, ROWS/128), 256, GEMM3_SMEM>>>(
        hh, hl, w4h, w4l, b4, x1, out, nullptr, nullptr, nullptr, ROWS, DM, D4);
}